// round 7
// baseline (speedup 1.0000x reference)
#include <cuda_runtime.h>
#include <cuda_bf16.h>
#include <cuda_fp16.h>
#include <math.h>
#include <stdint.h>

#define B 16
#define S 1024
#define H 256
#define NH 4
#define DH 64
#define H2 128
#define MROWS (B*S)   // 16384

// ---------------- scratch (static device globals) ----------------
__device__ __align__(16) __nv_bfloat16 g_xh[MROWS*H];
__device__ __align__(16) __nv_bfloat16 g_WqkT[512*H];                    // [Wq|Wk]^T
__device__ __align__(16) __nv_bfloat16 g_WmiT[384*H];                    // [Wm1|Wi1]^T
__device__ __align__(16) __nv_bfloat16 g_Wi2T[H*H];
__device__ __align__(16) __nv_bfloat16 g_We1T[H2*H];
__device__ __align__(16) __nv_bfloat16 g_qkh[MROWS*512];                 // packed q|k bf16
__device__ __align__(16) __nv_bfloat16 g_i1b[MROWS*H];
__device__ __align__(16) __nv_bfloat16 g_fb[MROWS*H];
__device__ float g_str[B*S];
__device__ float g_awsum[B*S];
__device__ float g_awm[B*S];
__device__ float g_colmean[B*S];
__device__ float g_base[B*H];

// ---------------- PTX helpers ----------------
__device__ __forceinline__ uint32_t smem_u32(const void* p) {
    return (uint32_t)__cvta_generic_to_shared(p);
}
__device__ __forceinline__ void ldm_x4(uint32_t* r, uint32_t a) {
    asm volatile("ldmatrix.sync.aligned.m8n8.x4.shared.b16 {%0,%1,%2,%3}, [%4];"
        : "=r"(r[0]), "=r"(r[1]), "=r"(r[2]), "=r"(r[3]) : "r"(a));
}
__device__ __forceinline__ void mma_bf16(float* c, const uint32_t* a, const uint32_t* b) {
    asm volatile(
        "mma.sync.aligned.m16n8k16.row.col.f32.bf16.bf16.f32 "
        "{%0,%1,%2,%3},{%4,%5,%6,%7},{%8,%9},{%0,%1,%2,%3};"
        : "+f"(c[0]), "+f"(c[1]), "+f"(c[2]), "+f"(c[3])
        : "r"(a[0]), "r"(a[1]), "r"(a[2]), "r"(a[3]), "r"(b[0]), "r"(b[1]));
}
__device__ __forceinline__ void cpa16(uint32_t dst, const void* src) {
    asm volatile("cp.async.cg.shared.global [%0], [%1], 16;" :: "r"(dst), "l"(src));
}
__device__ __forceinline__ void cpa_commit() { asm volatile("cp.async.commit_group;"); }
__device__ __forceinline__ void cpa_wait1() { asm volatile("cp.async.wait_group 1;"); }
__device__ __forceinline__ void cpa_wait0() { asm volatile("cp.async.wait_group 0;"); }

// half2-as-uint helpers
__device__ __forceinline__ uint32_t h2_ex2(uint32_t x) {
    uint32_t r; asm("ex2.approx.f16x2 %0, %1;" : "=r"(r) : "r"(x)); return r;
}
__device__ __forceinline__ uint32_t h2_add(uint32_t a, uint32_t b) {
    uint32_t r; asm("add.rn.f16x2 %0, %1, %2;" : "=r"(r) : "r"(a), "r"(b)); return r;
}
__device__ __forceinline__ uint32_t h2_mul(uint32_t a, uint32_t b) {
    uint32_t r; asm("mul.rn.f16x2 %0, %1, %2;" : "=r"(r) : "r"(a), "r"(b)); return r;
}
__device__ __forceinline__ uint32_t h2_pack(float a, float b) {
    __half2 h = __floats2half2_rn(a, b);
    return *reinterpret_cast<uint32_t*>(&h);
}
__device__ __forceinline__ float2 h2_unpack(uint32_t u) {
    return __half22float2(*reinterpret_cast<__half2*>(&u));
}

// ---------------- fused prep: x->bf16, weight transposes, zero awsum -------------
__global__ void prep_k(const float* __restrict__ x,
                       const float* __restrict__ Wq, const float* __restrict__ Wk,
                       const float* __restrict__ Wm1, const float* __restrict__ Wi1,
                       const float* __restrict__ Wi2, const float* __restrict__ We1) {
    int bid = blockIdx.x, t = threadIdx.x;
    if (bid < 4096) {                       // x -> xh (vec4)
        int i = bid * 1024 + t * 4;
        float4 v = *(const float4*)(x + i);
        __nv_bfloat162* dst = (__nv_bfloat162*)(g_xh + i);
        dst[0] = __floats2bfloat162_rn(v.x, v.y);
        dst[1] = __floats2bfloat162_rn(v.z, v.w);
        return;
    }
    bid -= 4096;
    if (bid < 256) {
        int o = bid * 256 + t; int n = o >> 8, k = o & 255;
        g_WqkT[o] = __float2bfloat16(Wq[k * 256 + n]);
        return;
    }
    bid -= 256;
    if (bid < 256) {
        int o = bid * 256 + t; int n = o >> 8, k = o & 255;
        g_WqkT[65536 + o] = __float2bfloat16(Wk[k * 256 + n]);
        return;
    }
    bid -= 256;
    if (bid < 128) {
        int o = bid * 256 + t; int n = o >> 8, k = o & 255;
        g_WmiT[o] = __float2bfloat16(Wm1[k * 128 + n]);
        return;
    }
    bid -= 128;
    if (bid < 256) {
        int o = bid * 256 + t; int n = o >> 8, k = o & 255;
        g_WmiT[128 * 256 + o] = __float2bfloat16(Wi1[k * 256 + n]);
        return;
    }
    bid -= 256;
    if (bid < 256) {
        int o = bid * 256 + t; int n = o >> 8, k = o & 255;
        g_Wi2T[o] = __float2bfloat16(Wi2[k * 256 + n]);
        return;
    }
    bid -= 256;
    if (bid < 128) {
        int o = bid * 256 + t; int n = o >> 8, k = o & 255;
        g_We1T[o] = __float2bfloat16(We1[k * 128 + n]);
        return;
    }
    bid -= 128;
    g_awsum[bid * 256 + t] = 0.f;
}

// ---------------- bf16 tensor-core GEMM (mma.sync), BT[n,k] operand --------------
template<int MODE>
__global__ void __launch_bounds__(256) gemm_mma(
    const __nv_bfloat16* __restrict__ Ah,
    const __nv_bfloat16* __restrict__ BTh,
    const float* __restrict__ bias0, const float* __restrict__ bias1,
    const float* __restrict__ hw, const float* __restrict__ hb,
    const float* __restrict__ fin,
    void* out0, void* out1)
{
    extern __shared__ char smem[];
    const int STB = 16384;
    int t = threadIdx.x, w = t >> 5, lane = t & 31;
    int row0 = blockIdx.y * 128, col0 = blockIdx.x * 128;
    int wm = w & 1, wn = w >> 1;
    int g = lane >> 2, tq = lane & 3;

    float acc[4][4][4];
#pragma unroll
    for (int mt = 0; mt < 4; mt++)
#pragma unroll
        for (int nt = 0; nt < 4; nt++)
#pragma unroll
            for (int r = 0; r < 4; r++) acc[mt][nt][r] = 0.f;

    uint32_t sbase = smem_u32(smem);

    auto load_stage = [&](int stage, int kt) {
        uint32_t sb = sbase + stage * STB;
#pragma unroll
        for (int i = 0; i < 2; i++) {
            int c = t + i * 256;
            int row = c >> 2, ch = c & 3;
            uint32_t d = (uint32_t)((row * 4 + (ch ^ ((row >> 1) & 3))) * 16);
            cpa16(sb + d, Ah + (size_t)(row0 + row) * 256 + kt * 32 + ch * 8);
            cpa16(sb + 8192 + d, BTh + (size_t)(col0 + row) * 256 + kt * 32 + ch * 8);
        }
    };

    load_stage(0, 0);
    cpa_commit();

    for (int kt = 0; kt < 8; kt++) {
        int st = kt & 1;
        if (kt < 7) { load_stage(st ^ 1, kt + 1); cpa_commit(); cpa_wait1(); }
        else cpa_wait0();
        __syncthreads();
        uint32_t sb = sbase + st * STB;
#pragma unroll
        for (int kk = 0; kk < 2; kk++) {
            uint32_t ah[4][4];
#pragma unroll
            for (int mt = 0; mt < 4; mt++) {
                int row = wm * 64 + mt * 16 + (lane & 15);
                int ch = kk * 2 + (lane >> 4);
                uint32_t off = (uint32_t)((row * 4 + (ch ^ ((row >> 1) & 3))) * 16);
                ldm_x4(ah[mt], sb + off);
            }
            uint32_t bh[4][2];
#pragma unroll
            for (int p = 0; p < 2; p++) {
                int row = wn * 32 + p * 16 + (lane & 7) + 8 * (lane >> 4);
                int ch = kk * 2 + ((lane >> 3) & 1);
                uint32_t off = (uint32_t)((row * 4 + (ch ^ ((row >> 1) & 3))) * 16);
                uint32_t r4[4];
                ldm_x4(r4, sb + 8192 + off);
                bh[2 * p][0] = r4[0]; bh[2 * p][1] = r4[1];
                bh[2 * p + 1][0] = r4[2]; bh[2 * p + 1][1] = r4[3];
            }
#pragma unroll
            for (int mt = 0; mt < 4; mt++)
#pragma unroll
                for (int nt = 0; nt < 4; nt++)
                    mma_bf16(acc[mt][nt], ah[mt], bh[nt]);
        }
        __syncthreads();
    }

    bool head = (MODE == 3) || (MODE == 1 && blockIdx.x == 0);
    float* st = (float*)smem;

#pragma unroll
    for (int mt = 0; mt < 4; mt++) {
        int rl = wm * 64 + mt * 16 + g;
#pragma unroll
        for (int nt = 0; nt < 4; nt++) {
            int cl = wn * 32 + nt * 8 + 2 * tq;
            int colb = col0 + cl;
#pragma unroll
            for (int half = 0; half < 2; half++) {
                int rr = row0 + rl + 8 * half;
                float v0 = acc[mt][nt][2 * half];
                float v1 = acc[mt][nt][2 * half + 1];
                if (MODE == 0) {
                    bool isk = (colb >= 256);
                    v0 += isk ? bias1[colb - 256] : bias0[colb];
                    v1 += isk ? bias1[colb - 255] : bias0[colb + 1];
                    *(__nv_bfloat162*)((__nv_bfloat16*)out0 + (size_t)rr * 512 + colb) =
                        __floats2bfloat162_rn(v0, v1);
                } else if (MODE == 1) {
                    if (head) {
                        v0 = fmaxf(v0 + bias0[colb], 0.f);
                        v1 = fmaxf(v1 + bias0[colb + 1], 0.f);
                        st[(rl + 8 * half) * 129 + cl] = v0;
                        st[(rl + 8 * half) * 129 + cl + 1] = v1;
                    } else {
                        int c2 = colb - 128;
                        v0 = fmaxf(v0 + bias1[c2], 0.f);
                        v1 = fmaxf(v1 + bias1[c2 + 1], 0.f);
                        *(__nv_bfloat162*)((__nv_bfloat16*)out1 + (size_t)rr * 256 + c2) =
                            __floats2bfloat162_rn(v0, v1);
                    }
                } else if (MODE == 2) {
                    v0 = 0.1f * tanhf(v0 + bias0[colb]);
                    v1 = 0.1f * tanhf(v1 + bias0[colb + 1]);
                    float cmv = g_colmean[rr] * (1.f / S);
                    int bb = row0 >> 10;
                    float f0 = g_base[bb * H + colb] + v0 * cmv;
                    float f1 = g_base[bb * H + colb + 1] + v1 * cmv;
                    *(__nv_bfloat162*)((__nv_bfloat16*)out0 + (size_t)rr * 256 + colb) =
                        __floats2bfloat162_rn(f0, f1);
                } else {   // MODE 3
                    v0 = fmaxf(v0 + bias0[colb], 0.f);
                    v1 = fmaxf(v1 + bias0[colb + 1], 0.f);
                    st[(rl + 8 * half) * 129 + cl] = v0;
                    st[(rl + 8 * half) * 129 + cl + 1] = v1;
                }
            }
        }
    }

    if (head) {
        __syncthreads();
        float wv[4];
#pragma unroll
        for (int i = 0; i < 4; i++) wv[i] = hw[lane + 32 * i];
        float hbv = hb[0];
        int bb = row0 >> 10;
#pragma unroll
        for (int rr = w * 16; rr < w * 16 + 16; rr++) {
            float s = 0.f;
#pragma unroll
            for (int i = 0; i < 4; i++) s += wv[i] * st[rr * 129 + lane + 32 * i];
#pragma unroll
            for (int o = 16; o; o >>= 1) s += __shfl_xor_sync(0xFFFFFFFFu, s, o);
            if (lane == 0) {
                float v = s + hbv;
                if (MODE == 1) ((float*)out0)[row0 + rr] = 1.f / (1.f + __expf(-v));
                else           ((float*)out0)[row0 + rr] = fin[bb] - v;
            }
        }
    }
}

// ---------------- attention column-sum (register-resident scores) ----------------
// smem: K 2x16K | Q 4K | colsum float[1024] | rpart[128] | rden[32]
#define ATTN_SMEM (32768 + 4096 + 4096 + 512 + 128)
__global__ void __launch_bounds__(256, 2) attn_mma() {
    extern __shared__ char smem[];
    char* Kst = smem;
    char* Qh = smem + 32768;
    float* colsum = (float*)(smem + 32768 + 4096);
    float* rpart = colsum + 1024;     // [4][32]
    float* rden = rpart + 128;        // [32]

    int t = threadIdx.x, w = t >> 5, lane = t & 31;
    int qt = blockIdx.x & 31;
    int bh = blockIdx.x >> 5;
    int b = bh >> 2, h = bh & 3;
    int q0 = qt * 32;
    int wm = w & 1, wn = w >> 1;
    int g = lane >> 2, tq = lane & 3;

    uint32_t kbase = smem_u32(Kst);
    uint32_t qbase = smem_u32(Qh);

    // zero colsum
#pragma unroll
    for (int jj = 0; jj < 4; jj++) colsum[t + jj * 256] = 0.f;

    // load Q tile (32x64), swizzled
    {
        int row = t >> 3, ch = t & 7;
        const __nv_bfloat16* sh = g_qkh + (size_t)(b * S + q0 + row) * 512 + h * DH + ch * 8;
        uint32_t d = (uint32_t)((row * 8 + (ch ^ (row & 7))) * 16);
        *(uint4*)(Qh + d) = *(const uint4*)sh;
    }

    auto load_K = [&](int stage, int kt) {
        uint32_t sbk = kbase + stage * 16384;
#pragma unroll
        for (int i = 0; i < 4; i++) {
            int c = t + i * 256;
            int j = c >> 3, ch = c & 7;
            uint32_t d = (uint32_t)((j * 8 + (ch ^ (j & 7))) * 16);
            size_t src = (size_t)(b * S + kt * 128 + j) * 512 + 256 + h * DH + ch * 8;
            cpa16(sbk + d, g_qkh + src);
        }
    };

    load_K(0, 0);
    cpa_commit();

    uint32_t sc[8][4][2];             // exp scores as half2, register-resident
    float rsum0 = 0.f, rsum1 = 0.f;
    const float CEXP = 0.125f * 1.44269504f;   // fold 1/sqrt(DH)/... into log2 scale

#pragma unroll
    for (int kt = 0; kt < 8; kt++) {
        int stg = kt & 1;
        if (kt < 7) { load_K(stg ^ 1, kt + 1); cpa_commit(); cpa_wait1(); }
        else cpa_wait0();
        __syncthreads();
        uint32_t sbk = kbase + stg * 16384;

        float acc[4][4];
#pragma unroll
        for (int nt = 0; nt < 4; nt++)
#pragma unroll
            for (int r = 0; r < 4; r++) acc[nt][r] = 0.f;

#pragma unroll
        for (int d16 = 0; d16 < 4; d16++) {
            uint32_t ah[4];
            {
                int row = wm * 16 + (lane & 15);
                int ch = d16 * 2 + (lane >> 4);
                uint32_t off = (uint32_t)((row * 8 + (ch ^ (row & 7))) * 16);
                ldm_x4(ah, qbase + off);
            }
            uint32_t bh2[4][2];
#pragma unroll
            for (int p = 0; p < 2; p++) {
                int j = wn * 32 + p * 16 + (lane & 7) + 8 * (lane >> 4);
                int ch = d16 * 2 + ((lane >> 3) & 1);
                uint32_t off = (uint32_t)((j * 8 + (ch ^ (j & 7))) * 16);
                uint32_t r4[4];
                ldm_x4(r4, sbk + off);
                bh2[2 * p][0] = r4[0]; bh2[2 * p][1] = r4[1];
                bh2[2 * p + 1][0] = r4[2]; bh2[2 * p + 1][1] = r4[3];
            }
#pragma unroll
            for (int nt = 0; nt < 4; nt++) mma_bf16(acc[nt], ah, bh2[nt]);
        }
#pragma unroll
        for (int nt = 0; nt < 4; nt++) {
            uint32_t e0 = h2_ex2(h2_pack(acc[nt][0] * CEXP, acc[nt][1] * CEXP));
            uint32_t e1 = h2_ex2(h2_pack(acc[nt][2] * CEXP, acc[nt][3] * CEXP));
            sc[kt][nt][0] = e0;
            sc[kt][nt][1] = e1;
            float2 f0 = h2_unpack(e0);
            float2 f1 = h2_unpack(e1);
            rsum0 += f0.x + f0.y;
            rsum1 += f1.x + f1.y;
        }
        __syncthreads();
    }

    // row sums: reduce over tq lanes, then over wn warps via smem
    rsum0 += __shfl_xor_sync(0xFFFFFFFFu, rsum0, 1);
    rsum0 += __shfl_xor_sync(0xFFFFFFFFu, rsum0, 2);
    rsum1 += __shfl_xor_sync(0xFFFFFFFFu, rsum1, 1);
    rsum1 += __shfl_xor_sync(0xFFFFFFFFu, rsum1, 2);
    if (tq == 0) {
        rpart[wn * 32 + wm * 16 + g] = rsum0;
        rpart[wn * 32 + wm * 16 + g + 8] = rsum1;
    }
    __syncthreads();
    if (t < 32)
        rden[t] = 1.f / (rpart[t] + rpart[32 + t] + rpart[64 + t] + rpart[96 + t]);
    __syncthreads();

    // scale by 1/rowsum (half2), shfl-reduce over 8 g-lanes, atomicAdd to colsum
    uint32_t hrd0, hrd1;
    {
        float rd0 = rden[wm * 16 + g];
        float rd1 = rden[wm * 16 + g + 8];
        hrd0 = h2_pack(rd0, rd0);
        hrd1 = h2_pack(rd1, rd1);
    }
#pragma unroll
    for (int kt = 0; kt < 8; kt++)
#pragma unroll
        for (int nt = 0; nt < 4; nt++) {
            uint32_t v = h2_add(h2_mul(sc[kt][nt][0], hrd0), h2_mul(sc[kt][nt][1], hrd1));
            v = h2_add(v, __shfl_xor_sync(0xFFFFFFFFu, v, 4));
            v = h2_add(v, __shfl_xor_sync(0xFFFFFFFFu, v, 8));
            v = h2_add(v, __shfl_xor_sync(0xFFFFFFFFu, v, 16));
            if (g == 0) {
                float2 f = h2_unpack(v);
                int colb = kt * 128 + wn * 32 + nt * 8 + 2 * tq;
                atomicAdd(&colsum[colb], f.x);
                atomicAdd(&colsum[colb + 1], f.y);
            }
        }
    __syncthreads();

    // colsum -> global accumulation
#pragma unroll
    for (int jj = 0; jj < 4; jj++) {
        int j = t + jj * 256;
        atomicAdd(&g_awsum[b * S + j], colsum[j]);
    }
}

// ---------------- colmean (parallel suffix scan) + base, fused -------------------
__global__ void __launch_bounds__(1024) colmean_base_k(const float* __restrict__ x) {
    __shared__ float s0[1024], s1[1024], cmb[1024], bacc[4][256];
    int b = blockIdx.x, j = threadIdx.x;
    s0[j] = g_str[b * S + j];
    __syncthreads();
    float* cur = s0; float* nxt = s1;
#pragma unroll
    for (int off = 1; off < 1024; off <<= 1) {
        float v = cur[j];
        if (j + off < 1024) v += cur[j + off];
        __syncthreads();
        nxt[j] = v;
        __syncthreads();
        float* tmp = cur; cur = nxt; nxt = tmp;
    }
    float awm = g_awsum[b * S + j] * (1.f / (NH * S));
    g_awm[b * S + j] = awm;
    float cmv = awm * cur[j] * (1.f / S);
    g_colmean[b * S + j] = cmv;
    cmb[j] = cmv;
    __syncthreads();
    int h = j & 255, sg = j >> 8;
    const float* xb = x + (size_t)b * S * H;
    float a = 0.f;
    for (int s = sg * 256; s < sg * 256 + 256; s++)
        a += xb[(size_t)s * H + h] * cmb[s];
    bacc[sg][h] = a;
    __syncthreads();
    if (j < 256)
        g_base[b * H + j] = (bacc[0][j] + bacc[1][j] + bacc[2][j] + bacc[3][j]) * (1.f / S);
}

// ---------------- cm output ----------------
__global__ void cm_k(float* __restrict__ out) {
    int bi = blockIdx.x;
    int b = bi >> 10, i = bi & 1023;
    float stv = g_str[bi];
    const float4* aw = (const float4*)(g_awm + b * S);
    float4* o = (float4*)(out + (size_t)bi * S);
    int j4 = threadIdx.x;
    float4 a = aw[j4];
    int j = j4 * 4;
    float4 v;
    v.x = (i >= j)     ? a.x * stv : 0.f;
    v.y = (i >= j + 1) ? a.y * stv : 0.f;
    v.z = (i >= j + 2) ? a.z * stv : 0.f;
    v.w = (i >= j + 3) ? a.w * stv : 0.f;
    o[j4] = v;
}

// ---------------- launch ----------------
extern "C" void kernel_launch(void* const* d_in, const int* in_sizes, int n_in,
                              void* d_out, int out_size) {
    const float* x    = (const float*)d_in[0];
    const float* fin  = (const float*)d_in[1];
    const float* Wq   = (const float*)d_in[3];
    const float* bq   = (const float*)d_in[4];
    const float* Wk   = (const float*)d_in[5];
    const float* bk   = (const float*)d_in[6];
    const float* Wm1  = (const float*)d_in[7];
    const float* bm1  = (const float*)d_in[8];
    const float* Wm2  = (const float*)d_in[9];
    const float* bm2  = (const float*)d_in[10];
    const float* Wi1  = (const float*)d_in[11];
    const float* bi1  = (const float*)d_in[12];
    const float* Wi2  = (const float*)d_in[13];
    const float* bi2  = (const float*)d_in[14];
    const float* We1  = (const float*)d_in[15];
    const float* be1  = (const float*)d_in[16];
    const float* We2  = (const float*)d_in[17];
    const float* be2  = (const float*)d_in[18];
    float* out = (float*)d_out;

    __nv_bfloat16 *pxh, *pWqkT, *pWmiT, *pWi2T, *pWe1T, *pqkh, *pi1b, *pfb;
    float *pstr;
    cudaGetSymbolAddress((void**)&pxh, g_xh);
    cudaGetSymbolAddress((void**)&pWqkT, g_WqkT);
    cudaGetSymbolAddress((void**)&pWmiT, g_WmiT);
    cudaGetSymbolAddress((void**)&pWi2T, g_Wi2T);
    cudaGetSymbolAddress((void**)&pWe1T, g_We1T);
    cudaGetSymbolAddress((void**)&pqkh, g_qkh);
    cudaGetSymbolAddress((void**)&pi1b, g_i1b);
    cudaGetSymbolAddress((void**)&pfb, g_fb);
    cudaGetSymbolAddress((void**)&pstr, g_str);

    const int SM_1P = 32768, SM_HEAD = 66048;
    cudaFuncSetAttribute(gemm_mma<0>, cudaFuncAttributeMaxDynamicSharedMemorySize, SM_1P);
    cudaFuncSetAttribute(gemm_mma<1>, cudaFuncAttributeMaxDynamicSharedMemorySize, SM_HEAD);
    cudaFuncSetAttribute(gemm_mma<2>, cudaFuncAttributeMaxDynamicSharedMemorySize, SM_1P);
    cudaFuncSetAttribute(gemm_mma<3>, cudaFuncAttributeMaxDynamicSharedMemorySize, SM_HEAD);
    cudaFuncSetAttribute(attn_mma, cudaFuncAttributeMaxDynamicSharedMemorySize, ATTN_SMEM);

    // 1. prep (conversions + transposes + zero awsum)
    prep_k<<<5440, 256>>>(x, Wq, Wk, Wm1, Wi1, Wi2, We1);

    // 2. QK projection (1-pass) -> packed q|k bf16
    gemm_mma<0><<<dim3(4,128), 256, SM_1P>>>(pxh, pWqkT, bq, bk,
                                             nullptr, nullptr, nullptr, pqkh, nullptr);
    // 3. M1|I1 + fused strengths head
    gemm_mma<1><<<dim3(3,128), 256, SM_HEAD>>>(pxh, pWmiT, bm1, bi1,
                                               Wm2, bm2, nullptr, pstr, pi1b);
    // 4. attention column sums
    attn_mma<<<B*NH*32, 256, ATTN_SMEM>>>();

    // 5. colmean (scan) + base
    colmean_base_k<<<B, 1024>>>(x);

    // 6. I2 + fused feats
    gemm_mma<2><<<dim3(2,128), 256, SM_1P>>>(pi1b, pWi2T, bi2, nullptr,
                                             nullptr, nullptr, nullptr, pfb, nullptr);
    // 7. E1 + fused credit head -> out[0 : B*S]
    gemm_mma<3><<<dim3(1,128), 256, SM_HEAD>>>(pfb, pWe1T, be1, nullptr,
                                               We2, be2, fin, out, nullptr);
    // 8. cm -> out[B*S : ]
    cm_k<<<MROWS, 256>>>(out + B*S);
}

// round 8
// speedup vs baseline: 1.1720x; 1.1720x over previous
#include <cuda_runtime.h>
#include <cuda_bf16.h>
#include <cuda_fp16.h>
#include <math.h>
#include <stdint.h>

#define B 16
#define S 1024
#define H 256
#define NH 4
#define DH 64
#define H2 128
#define MROWS (B*S)   // 16384

// ---------------- scratch (static device globals) ----------------
__device__ __align__(16) __nv_bfloat16 g_xh[MROWS*H];
__device__ __align__(16) __nv_bfloat16 g_WqkT[512*H];                    // [Wq|Wk]^T
__device__ __align__(16) __nv_bfloat16 g_WmiT[384*H];                    // [Wm1|Wi1]^T
__device__ __align__(16) __nv_bfloat16 g_Wi2T[H*H];
__device__ __align__(16) __nv_bfloat16 g_We1T[H2*H];
__device__ __align__(16) __nv_bfloat16 g_qkh[MROWS*512];                 // packed q|k bf16
__device__ __align__(16) __nv_bfloat16 g_i1b[MROWS*H];
__device__ __align__(16) __nv_bfloat16 g_fb[MROWS*H];
__device__ float g_str[B*S];
__device__ float g_awsum[B*S];
__device__ float g_awm[B*S];
__device__ float g_colmean[B*S];
__device__ float g_base[B*H];

// ---------------- PTX helpers ----------------
__device__ __forceinline__ uint32_t smem_u32(const void* p) {
    return (uint32_t)__cvta_generic_to_shared(p);
}
__device__ __forceinline__ void ldm_x4(uint32_t* r, uint32_t a) {
    asm volatile("ldmatrix.sync.aligned.m8n8.x4.shared.b16 {%0,%1,%2,%3}, [%4];"
        : "=r"(r[0]), "=r"(r[1]), "=r"(r[2]), "=r"(r[3]) : "r"(a));
}
__device__ __forceinline__ void mma_bf16(float* c, const uint32_t* a, const uint32_t* b) {
    asm volatile(
        "mma.sync.aligned.m16n8k16.row.col.f32.bf16.bf16.f32 "
        "{%0,%1,%2,%3},{%4,%5,%6,%7},{%8,%9},{%0,%1,%2,%3};"
        : "+f"(c[0]), "+f"(c[1]), "+f"(c[2]), "+f"(c[3])
        : "r"(a[0]), "r"(a[1]), "r"(a[2]), "r"(a[3]), "r"(b[0]), "r"(b[1]));
}
__device__ __forceinline__ void cpa16(uint32_t dst, const void* src) {
    asm volatile("cp.async.cg.shared.global [%0], [%1], 16;" :: "r"(dst), "l"(src));
}
__device__ __forceinline__ void cpa_commit() { asm volatile("cp.async.commit_group;"); }
__device__ __forceinline__ void cpa_wait1() { asm volatile("cp.async.wait_group 1;"); }
__device__ __forceinline__ void cpa_wait0() { asm volatile("cp.async.wait_group 0;"); }

__device__ __forceinline__ uint32_t h2_ex2(uint32_t x) {
    uint32_t r; asm("ex2.approx.f16x2 %0, %1;" : "=r"(r) : "r"(x)); return r;
}
__device__ __forceinline__ uint32_t h2_pack(float a, float b) {
    __half2 h = __floats2half2_rn(a, b);
    return *reinterpret_cast<uint32_t*>(&h);
}
__device__ __forceinline__ float2 h2_unpack(uint32_t u) {
    return __half22float2(*reinterpret_cast<__half2*>(&u));
}

// ---------------- fused prep: x->bf16, weight transposes, zero awsum -------------
__global__ void prep_k(const float* __restrict__ x,
                       const float* __restrict__ Wq, const float* __restrict__ Wk,
                       const float* __restrict__ Wm1, const float* __restrict__ Wi1,
                       const float* __restrict__ Wi2, const float* __restrict__ We1) {
    int bid = blockIdx.x, t = threadIdx.x;
    if (bid < 4096) {                       // x -> xh (vec4)
        int i = bid * 1024 + t * 4;
        float4 v = *(const float4*)(x + i);
        __nv_bfloat162* dst = (__nv_bfloat162*)(g_xh + i);
        dst[0] = __floats2bfloat162_rn(v.x, v.y);
        dst[1] = __floats2bfloat162_rn(v.z, v.w);
        return;
    }
    bid -= 4096;
    if (bid < 256) {
        int o = bid * 256 + t; int n = o >> 8, k = o & 255;
        g_WqkT[o] = __float2bfloat16(Wq[k * 256 + n]);
        return;
    }
    bid -= 256;
    if (bid < 256) {
        int o = bid * 256 + t; int n = o >> 8, k = o & 255;
        g_WqkT[65536 + o] = __float2bfloat16(Wk[k * 256 + n]);
        return;
    }
    bid -= 256;
    if (bid < 128) {
        int o = bid * 256 + t; int n = o >> 8, k = o & 255;
        g_WmiT[o] = __float2bfloat16(Wm1[k * 128 + n]);
        return;
    }
    bid -= 128;
    if (bid < 256) {
        int o = bid * 256 + t; int n = o >> 8, k = o & 255;
        g_WmiT[128 * 256 + o] = __float2bfloat16(Wi1[k * 256 + n]);
        return;
    }
    bid -= 256;
    if (bid < 256) {
        int o = bid * 256 + t; int n = o >> 8, k = o & 255;
        g_Wi2T[o] = __float2bfloat16(Wi2[k * 256 + n]);
        return;
    }
    bid -= 256;
    if (bid < 128) {
        int o = bid * 256 + t; int n = o >> 8, k = o & 255;
        g_We1T[o] = __float2bfloat16(We1[k * 128 + n]);
        return;
    }
    bid -= 128;
    g_awsum[bid * 256 + t] = 0.f;
}

// ---------------- shared GEMM pipeline body (macro-free via inline) --------------
// computes acc[4][4][4] for C tile [row0:+128, Bt cols 0:128], A pitch 256
__device__ __forceinline__ void gemm_core(
    const __nv_bfloat16* __restrict__ Ah, const __nv_bfloat16* __restrict__ Bt,
    int row0, uint32_t sbase, int t, int wm, int wn, int lane,
    float acc[4][4][4])
{
    const int STB = 16384;
    auto load_stage = [&](int stage, int kt) {
        uint32_t sb = sbase + stage * STB;
#pragma unroll
        for (int i = 0; i < 2; i++) {
            int c = t + i * 256;
            int row = c >> 2, ch = c & 3;
            uint32_t d = (uint32_t)((row * 4 + (ch ^ ((row >> 1) & 3))) * 16);
            cpa16(sb + d, Ah + (size_t)(row0 + row) * 256 + kt * 32 + ch * 8);
            cpa16(sb + 8192 + d, Bt + (size_t)row * 256 + kt * 32 + ch * 8);
        }
    };
    load_stage(0, 0);
    cpa_commit();
    for (int kt = 0; kt < 8; kt++) {
        int st = kt & 1;
        if (kt < 7) { load_stage(st ^ 1, kt + 1); cpa_commit(); cpa_wait1(); }
        else cpa_wait0();
        __syncthreads();
        uint32_t sb = sbase + st * STB;
#pragma unroll
        for (int kk = 0; kk < 2; kk++) {
            uint32_t ah[4][4];
#pragma unroll
            for (int mt = 0; mt < 4; mt++) {
                int row = wm * 64 + mt * 16 + (lane & 15);
                int ch = kk * 2 + (lane >> 4);
                uint32_t off = (uint32_t)((row * 4 + (ch ^ ((row >> 1) & 3))) * 16);
                ldm_x4(ah[mt], sb + off);
            }
            uint32_t bh[4][2];
#pragma unroll
            for (int p = 0; p < 2; p++) {
                int row = wn * 32 + p * 16 + (lane & 7) + 8 * (lane >> 4);
                int ch = kk * 2 + ((lane >> 3) & 1);
                uint32_t off = (uint32_t)((row * 4 + (ch ^ ((row >> 1) & 3))) * 16);
                uint32_t r4[4];
                ldm_x4(r4, sb + 8192 + off);
                bh[2 * p][0] = r4[0]; bh[2 * p][1] = r4[1];
                bh[2 * p + 1][0] = r4[2]; bh[2 * p + 1][1] = r4[3];
            }
#pragma unroll
            for (int mt = 0; mt < 4; mt++)
#pragma unroll
                for (int nt = 0; nt < 4; nt++)
                    mma_bf16(acc[mt][nt], ah[mt], bh[nt]);
        }
        __syncthreads();
    }
}

// ---------------- merged QK | M1(strengths) | I1 GEMM ----------------------------
// grid (7, 128): bx<4 -> QK cols bx*128; bx==4 -> strengths head; bx in {5,6} -> i1
__global__ void __launch_bounds__(256) gemm_qkmi(
    const __nv_bfloat16* __restrict__ Ah,
    const float* __restrict__ bq, const float* __restrict__ bk,
    const float* __restrict__ bm1, const float* __restrict__ bi1,
    const float* __restrict__ Wm2, const float* __restrict__ bm2)
{
    extern __shared__ char smem[];
    int t = threadIdx.x, w = t >> 5, lane = t & 31;
    int bx = blockIdx.x;
    int row0 = blockIdx.y * 128;
    int wm = w & 1, wn = w >> 1;
    int g = lane >> 2, tq = lane & 3;

    const __nv_bfloat16* Bt = (bx < 4) ? (g_WqkT + (size_t)bx * 128 * 256)
                                       : (g_WmiT + (size_t)(bx - 4) * 128 * 256);

    float acc[4][4][4];
#pragma unroll
    for (int mt = 0; mt < 4; mt++)
#pragma unroll
        for (int nt = 0; nt < 4; nt++)
#pragma unroll
            for (int r = 0; r < 4; r++) acc[mt][nt][r] = 0.f;

    gemm_core(Ah, Bt, row0, smem_u32(smem), t, wm, wn, lane, acc);

    bool head = (bx == 4);
    float* st = (float*)smem;

#pragma unroll
    for (int mt = 0; mt < 4; mt++) {
        int rl = wm * 64 + mt * 16 + g;
#pragma unroll
        for (int nt = 0; nt < 4; nt++) {
            int cl = wn * 32 + nt * 8 + 2 * tq;
#pragma unroll
            for (int half = 0; half < 2; half++) {
                int rr = row0 + rl + 8 * half;
                float v0 = acc[mt][nt][2 * half];
                float v1 = acc[mt][nt][2 * half + 1];
                if (bx < 4) {
                    int gcol = bx * 128 + cl;
                    bool isk = (gcol >= 256);
                    v0 += isk ? bk[gcol - 256] : bq[gcol];
                    v1 += isk ? bk[gcol - 255] : bq[gcol + 1];
                    *(__nv_bfloat162*)(g_qkh + (size_t)rr * 512 + gcol) =
                        __floats2bfloat162_rn(v0, v1);
                } else if (head) {
                    v0 = fmaxf(v0 + bm1[cl], 0.f);
                    v1 = fmaxf(v1 + bm1[cl + 1], 0.f);
                    st[(rl + 8 * half) * 129 + cl] = v0;
                    st[(rl + 8 * half) * 129 + cl + 1] = v1;
                } else {
                    int c2 = (bx - 5) * 128 + cl;
                    v0 = fmaxf(v0 + bi1[c2], 0.f);
                    v1 = fmaxf(v1 + bi1[c2 + 1], 0.f);
                    *(__nv_bfloat162*)(g_i1b + (size_t)rr * 256 + c2) =
                        __floats2bfloat162_rn(v0, v1);
                }
            }
        }
    }

    if (head) {
        __syncthreads();
        float wv[4];
#pragma unroll
        for (int i = 0; i < 4; i++) wv[i] = Wm2[lane + 32 * i];
        float hbv = bm2[0];
#pragma unroll
        for (int rr = w * 16; rr < w * 16 + 16; rr++) {
            float s = 0.f;
#pragma unroll
            for (int i = 0; i < 4; i++) s += wv[i] * st[rr * 129 + lane + 32 * i];
#pragma unroll
            for (int o = 16; o; o >>= 1) s += __shfl_xor_sync(0xFFFFFFFFu, s, o);
            if (lane == 0)
                g_str[row0 + rr] = 1.f / (1.f + __expf(-(s + hbv)));
        }
    }
}

// ---------------- I2+feats (MODE 2) and E1+credit (MODE 3) -----------------------
template<int MODE>
__global__ void __launch_bounds__(256) gemm_mma(
    const __nv_bfloat16* __restrict__ Ah,
    const __nv_bfloat16* __restrict__ BTh,
    const float* __restrict__ bias0,
    const float* __restrict__ hw, const float* __restrict__ hb,
    const float* __restrict__ fin,
    void* out0)
{
    extern __shared__ char smem[];
    int t = threadIdx.x, w = t >> 5, lane = t & 31;
    int row0 = blockIdx.y * 128, col0 = blockIdx.x * 128;
    int wm = w & 1, wn = w >> 1;
    int g = lane >> 2, tq = lane & 3;

    float acc[4][4][4];
#pragma unroll
    for (int mt = 0; mt < 4; mt++)
#pragma unroll
        for (int nt = 0; nt < 4; nt++)
#pragma unroll
            for (int r = 0; r < 4; r++) acc[mt][nt][r] = 0.f;

    gemm_core(Ah, BTh + (size_t)col0 * 256, row0, smem_u32(smem), t, wm, wn, lane, acc);

    float* st = (float*)smem;

#pragma unroll
    for (int mt = 0; mt < 4; mt++) {
        int rl = wm * 64 + mt * 16 + g;
#pragma unroll
        for (int nt = 0; nt < 4; nt++) {
            int cl = wn * 32 + nt * 8 + 2 * tq;
            int colb = col0 + cl;
#pragma unroll
            for (int half = 0; half < 2; half++) {
                int rr = row0 + rl + 8 * half;
                float v0 = acc[mt][nt][2 * half];
                float v1 = acc[mt][nt][2 * half + 1];
                if (MODE == 2) {
                    v0 = 0.1f * tanhf(v0 + bias0[colb]);
                    v1 = 0.1f * tanhf(v1 + bias0[colb + 1]);
                    float cmv = g_colmean[rr] * (1.f / S);
                    int bb = row0 >> 10;
                    float f0 = g_base[bb * H + colb] + v0 * cmv;
                    float f1 = g_base[bb * H + colb + 1] + v1 * cmv;
                    *(__nv_bfloat162*)((__nv_bfloat16*)out0 + (size_t)rr * 256 + colb) =
                        __floats2bfloat162_rn(f0, f1);
                } else {
                    v0 = fmaxf(v0 + bias0[colb], 0.f);
                    v1 = fmaxf(v1 + bias0[colb + 1], 0.f);
                    st[(rl + 8 * half) * 129 + cl] = v0;
                    st[(rl + 8 * half) * 129 + cl + 1] = v1;
                }
            }
        }
    }

    if (MODE == 3) {
        __syncthreads();
        float wv[4];
#pragma unroll
        for (int i = 0; i < 4; i++) wv[i] = hw[lane + 32 * i];
        float hbv = hb[0];
        int bb = row0 >> 10;
#pragma unroll
        for (int rr = w * 16; rr < w * 16 + 16; rr++) {
            float s = 0.f;
#pragma unroll
            for (int i = 0; i < 4; i++) s += wv[i] * st[rr * 129 + lane + 32 * i];
#pragma unroll
            for (int o = 16; o; o >>= 1) s += __shfl_xor_sync(0xFFFFFFFFu, s, o);
            if (lane == 0)
                ((float*)out0)[row0 + rr] = fin[bb] - (s + hbv);
        }
    }
}

// ---------------- attention column-sum (fp16 Es, ex2.f16x2, reg row sums) --------
#define ES_PITCH 1048
#define ATTN_SMEM (32768 + 4096 + 32*ES_PITCH*2 + 512 + 128)
__global__ void __launch_bounds__(256) attn_mma() {
    extern __shared__ char smem[];
    char* Kst = smem;
    char* Qh = smem + 32768;
    __half* Es = (__half*)(Qh + 4096);
    float* rpart = (float*)(smem + 32768 + 4096 + 32 * ES_PITCH * 2); // [4][32]
    float* rden = rpart + 128;

    int t = threadIdx.x, w = t >> 5, lane = t & 31;
    int qt = blockIdx.x & 31;
    int bh = blockIdx.x >> 5;
    int b = bh >> 2, h = bh & 3;
    int q0 = qt * 32;
    int wm = w & 1, wn = w >> 1;
    int g = lane >> 2, tq = lane & 3;

    uint32_t kbase = smem_u32(Kst);
    uint32_t qbase = smem_u32(Qh);

    // load Q tile (32x64), swizzled
    {
        int row = t >> 3, ch = t & 7;
        const __nv_bfloat16* sh = g_qkh + (size_t)(b * S + q0 + row) * 512 + h * DH + ch * 8;
        uint32_t d = (uint32_t)((row * 8 + (ch ^ (row & 7))) * 16);
        *(uint4*)(Qh + d) = *(const uint4*)sh;
    }

    auto load_K = [&](int stage, int kt) {
        uint32_t sbk = kbase + stage * 16384;
#pragma unroll
        for (int i = 0; i < 4; i++) {
            int c = t + i * 256;
            int j = c >> 3, ch = c & 7;
            uint32_t d = (uint32_t)((j * 8 + (ch ^ (j & 7))) * 16);
            size_t src = (size_t)(b * S + kt * 128 + j) * 512 + 256 + h * DH + ch * 8;
            cpa16(sbk + d, g_qkh + src);
        }
    };

    load_K(0, 0);
    cpa_commit();

    float rsum0 = 0.f, rsum1 = 0.f;
    const float CEXP = 0.125f * 1.44269504f;

    for (int kt = 0; kt < 8; kt++) {
        int stg = kt & 1;
        if (kt < 7) { load_K(stg ^ 1, kt + 1); cpa_commit(); cpa_wait1(); }
        else cpa_wait0();
        __syncthreads();
        uint32_t sbk = kbase + stg * 16384;

        float acc[4][4];
#pragma unroll
        for (int nt = 0; nt < 4; nt++)
#pragma unroll
            for (int r = 0; r < 4; r++) acc[nt][r] = 0.f;

#pragma unroll
        for (int d16 = 0; d16 < 4; d16++) {
            uint32_t ah[4];
            {
                int row = wm * 16 + (lane & 15);
                int ch = d16 * 2 + (lane >> 4);
                uint32_t off = (uint32_t)((row * 8 + (ch ^ (row & 7))) * 16);
                ldm_x4(ah, qbase + off);
            }
            uint32_t bh2[4][2];
#pragma unroll
            for (int p = 0; p < 2; p++) {
                int j = wn * 32 + p * 16 + (lane & 7) + 8 * (lane >> 4);
                int ch = d16 * 2 + ((lane >> 3) & 1);
                uint32_t off = (uint32_t)((j * 8 + (ch ^ (j & 7))) * 16);
                uint32_t r4[4];
                ldm_x4(r4, sbk + off);
                bh2[2 * p][0] = r4[0]; bh2[2 * p][1] = r4[1];
                bh2[2 * p + 1][0] = r4[2]; bh2[2 * p + 1][1] = r4[3];
            }
#pragma unroll
            for (int nt = 0; nt < 4; nt++) mma_bf16(acc[nt], ah, bh2[nt]);
        }
#pragma unroll
        for (int nt = 0; nt < 4; nt++) {
            int colb = kt * 128 + wn * 32 + nt * 8 + 2 * tq;
            uint32_t e0 = h2_ex2(h2_pack(acc[nt][0] * CEXP, acc[nt][1] * CEXP));
            uint32_t e1 = h2_ex2(h2_pack(acc[nt][2] * CEXP, acc[nt][3] * CEXP));
            float2 f0 = h2_unpack(e0);
            float2 f1 = h2_unpack(e1);
            rsum0 += f0.x + f0.y;
            rsum1 += f1.x + f1.y;
            int r0 = wm * 16 + g;
            *(uint32_t*)&Es[r0 * ES_PITCH + colb] = e0;
            *(uint32_t*)&Es[(r0 + 8) * ES_PITCH + colb] = e1;
        }
        __syncthreads();
    }

    // row sums: reduce over tq lanes, then over wn warps via smem
    rsum0 += __shfl_xor_sync(0xFFFFFFFFu, rsum0, 1);
    rsum0 += __shfl_xor_sync(0xFFFFFFFFu, rsum0, 2);
    rsum1 += __shfl_xor_sync(0xFFFFFFFFu, rsum1, 1);
    rsum1 += __shfl_xor_sync(0xFFFFFFFFu, rsum1, 2);
    if (tq == 0) {
        rpart[wn * 32 + wm * 16 + g] = rsum0;
        rpart[wn * 32 + wm * 16 + g + 8] = rsum1;
    }
    __syncthreads();
    if (t < 32)
        rden[t] = 1.f / (rpart[t] + rpart[32 + t] + rpart[64 + t] + rpart[96 + t]);
    __syncthreads();

    // column sums (half2 reads) -> global accumulation
#pragma unroll
    for (int jj = 0; jj < 2; jj++) {
        int j2 = t + jj * 256;            // half2 index (0..511)
        float sx = 0.f, sy = 0.f;
#pragma unroll
        for (int r = 0; r < 32; r++) {
            float2 e = __half22float2(((__half2*)(Es + r * ES_PITCH))[j2]);
            float rd = rden[r];
            sx += e.x * rd;
            sy += e.y * rd;
        }
        atomicAdd(&g_awsum[b * S + 2 * j2], sx);
        atomicAdd(&g_awsum[b * S + 2 * j2 + 1], sy);
    }
}

// ---------------- colmean (parallel suffix scan) + base (bf16 x), fused ----------
__global__ void __launch_bounds__(1024) colmean_base_k() {
    __shared__ float s0[1024], s1[1024], cmb[1024], bacc[4][256];
    int b = blockIdx.x, j = threadIdx.x;
    s0[j] = g_str[b * S + j];
    __syncthreads();
    float* cur = s0; float* nxt = s1;
#pragma unroll
    for (int off = 1; off < 1024; off <<= 1) {
        float v = cur[j];
        if (j + off < 1024) v += cur[j + off];
        __syncthreads();
        nxt[j] = v;
        __syncthreads();
        float* tmp = cur; cur = nxt; nxt = tmp;
    }
    float awm = g_awsum[b * S + j] * (1.f / (NH * S));
    g_awm[b * S + j] = awm;
    float cmv = awm * cur[j] * (1.f / S);
    g_colmean[b * S + j] = cmv;
    cmb[j] = cmv;
    __syncthreads();
    int h = j & 255, sg = j >> 8;
    const __nv_bfloat16* xb = g_xh + (size_t)b * S * H;
    float a = 0.f;
    for (int s = sg * 256; s < sg * 256 + 256; s++)
        a += __bfloat162float(xb[(size_t)s * H + h]) * cmb[s];
    bacc[sg][h] = a;
    __syncthreads();
    if (j < 256)
        g_base[b * H + j] = (bacc[0][j] + bacc[1][j] + bacc[2][j] + bacc[3][j]) * (1.f / S);
}

// ---------------- cm output ----------------
__global__ void cm_k(float* __restrict__ out) {
    int bi = blockIdx.x;
    int b = bi >> 10, i = bi & 1023;
    float stv = g_str[bi];
    const float4* aw = (const float4*)(g_awm + b * S);
    float4* o = (float4*)(out + (size_t)bi * S);
    int j4 = threadIdx.x;
    float4 a = aw[j4];
    int j = j4 * 4;
    float4 v;
    v.x = (i >= j)     ? a.x * stv : 0.f;
    v.y = (i >= j + 1) ? a.y * stv : 0.f;
    v.z = (i >= j + 2) ? a.z * stv : 0.f;
    v.w = (i >= j + 3) ? a.w * stv : 0.f;
    o[j4] = v;
}

// ---------------- launch ----------------
extern "C" void kernel_launch(void* const* d_in, const int* in_sizes, int n_in,
                              void* d_out, int out_size) {
    const float* x    = (const float*)d_in[0];
    const float* fin  = (const float*)d_in[1];
    const float* Wq   = (const float*)d_in[3];
    const float* bq   = (const float*)d_in[4];
    const float* Wk   = (const float*)d_in[5];
    const float* bk   = (const float*)d_in[6];
    const float* Wm1  = (const float*)d_in[7];
    const float* bm1  = (const float*)d_in[8];
    const float* Wm2  = (const float*)d_in[9];
    const float* bm2  = (const float*)d_in[10];
    const float* Wi1  = (const float*)d_in[11];
    const float* bi1  = (const float*)d_in[12];
    const float* Wi2  = (const float*)d_in[13];
    const float* bi2  = (const float*)d_in[14];
    const float* We1  = (const float*)d_in[15];
    const float* be1  = (const float*)d_in[16];
    const float* We2  = (const float*)d_in[17];
    const float* be2  = (const float*)d_in[18];
    float* out = (float*)d_out;

    __nv_bfloat16 *pxh, *pWi2T, *pWe1T, *pi1b, *pfb;
    cudaGetSymbolAddress((void**)&pxh, g_xh);
    cudaGetSymbolAddress((void**)&pWi2T, g_Wi2T);
    cudaGetSymbolAddress((void**)&pWe1T, g_We1T);
    cudaGetSymbolAddress((void**)&pi1b, g_i1b);
    cudaGetSymbolAddress((void**)&pfb, g_fb);

    const int SM_1P = 32768, SM_HEAD = 66048;
    cudaFuncSetAttribute(gemm_qkmi, cudaFuncAttributeMaxDynamicSharedMemorySize, SM_HEAD);
    cudaFuncSetAttribute(gemm_mma<2>, cudaFuncAttributeMaxDynamicSharedMemorySize, SM_1P);
    cudaFuncSetAttribute(gemm_mma<3>, cudaFuncAttributeMaxDynamicSharedMemorySize, SM_HEAD);
    cudaFuncSetAttribute(attn_mma, cudaFuncAttributeMaxDynamicSharedMemorySize, ATTN_SMEM);

    // 1. prep (conversions + transposes + zero awsum)
    prep_k<<<5440, 256>>>(x, Wq, Wk, Wm1, Wi1, Wi2, We1);

    // 2. merged QK | strengths | I1
    gemm_qkmi<<<dim3(7,128), 256, SM_HEAD>>>(pxh, bq, bk, bm1, bi1, Wm2, bm2);

    // 3. attention column sums
    attn_mma<<<B*NH*32, 256, ATTN_SMEM>>>();

    // 4. colmean (scan) + base
    colmean_base_k<<<B, 1024>>>();

    // 5. I2 + fused feats
    gemm_mma<2><<<dim3(2,128), 256, SM_1P>>>(pi1b, pWi2T, bi2,
                                             nullptr, nullptr, nullptr, pfb);
    // 6. E1 + fused credit head -> out[0 : B*S]
    gemm_mma<3><<<dim3(1,128), 256, SM_HEAD>>>(pfb, pWe1T, be1,
                                               We2, be2, fin, out);
    // 7. cm -> out[B*S : ]
    cm_k<<<MROWS, 256>>>(out + B*S);
}

// round 9
// speedup vs baseline: 1.2426x; 1.0603x over previous
#include <cuda_runtime.h>
#include <cuda_bf16.h>
#include <cuda_fp16.h>
#include <math.h>
#include <stdint.h>

#define B 16
#define S 1024
#define H 256
#define NH 4
#define DH 64
#define H2 128
#define MROWS (B*S)   // 16384

// ---------------- scratch (static device globals) ----------------
__device__ __align__(16) __nv_bfloat16 g_xh[MROWS*H];
__device__ __align__(16) __nv_bfloat16 g_WqkT[512*H];                    // [Wq|Wk]^T
__device__ __align__(16) __nv_bfloat16 g_WmiT[384*H];                    // [Wm1|Wi1]^T
__device__ __align__(16) __nv_bfloat16 g_Wi2T[H*H];
__device__ __align__(16) __nv_bfloat16 g_We1T[H2*H];
__device__ __align__(16) __nv_bfloat16 g_qkh[MROWS*512];                 // packed q|k bf16
__device__ __align__(16) __nv_bfloat16 g_i1b[MROWS*H];
__device__ __align__(16) __nv_bfloat16 g_fb[MROWS*H];
__device__ float g_str[B*S];
__device__ float g_awsum[B*S];
__device__ float g_awm[B*S];
__device__ float g_colmean[B*S];
__device__ float g_base[B*H];

// ---------------- PTX helpers ----------------
__device__ __forceinline__ uint32_t smem_u32(const void* p) {
    return (uint32_t)__cvta_generic_to_shared(p);
}
__device__ __forceinline__ void ldm_x4(uint32_t* r, uint32_t a) {
    asm volatile("ldmatrix.sync.aligned.m8n8.x4.shared.b16 {%0,%1,%2,%3}, [%4];"
        : "=r"(r[0]), "=r"(r[1]), "=r"(r[2]), "=r"(r[3]) : "r"(a));
}
__device__ __forceinline__ void mma_bf16(float* c, const uint32_t* a, const uint32_t* b) {
    asm volatile(
        "mma.sync.aligned.m16n8k16.row.col.f32.bf16.bf16.f32 "
        "{%0,%1,%2,%3},{%4,%5,%6,%7},{%8,%9},{%0,%1,%2,%3};"
        : "+f"(c[0]), "+f"(c[1]), "+f"(c[2]), "+f"(c[3])
        : "r"(a[0]), "r"(a[1]), "r"(a[2]), "r"(a[3]), "r"(b[0]), "r"(b[1]));
}
__device__ __forceinline__ void cpa16(uint32_t dst, const void* src) {
    asm volatile("cp.async.cg.shared.global [%0], [%1], 16;" :: "r"(dst), "l"(src));
}
__device__ __forceinline__ void cpa_commit() { asm volatile("cp.async.commit_group;"); }
__device__ __forceinline__ void cpa_wait1() { asm volatile("cp.async.wait_group 1;"); }
__device__ __forceinline__ void cpa_wait0() { asm volatile("cp.async.wait_group 0;"); }

__device__ __forceinline__ uint32_t h2_ex2(uint32_t x) {
    uint32_t r; asm("ex2.approx.f16x2 %0, %1;" : "=r"(r) : "r"(x)); return r;
}
__device__ __forceinline__ uint32_t h2_pack(float a, float b) {
    __half2 h = __floats2half2_rn(a, b);
    return *reinterpret_cast<uint32_t*>(&h);
}
__device__ __forceinline__ float2 h2_unpack(uint32_t u) {
    return __half22float2(*reinterpret_cast<__half2*>(&u));
}

// ---------------- fused prep: x->bf16, weight transposes, zero awsum+base --------
// grid = 4096 + 256 + 256 + 128 + 256 + 256 + 128 + 64 + 16 = 5456
__global__ void prep_k(const float* __restrict__ x,
                       const float* __restrict__ Wq, const float* __restrict__ Wk,
                       const float* __restrict__ Wm1, const float* __restrict__ Wi1,
                       const float* __restrict__ Wi2, const float* __restrict__ We1) {
    int bid = blockIdx.x, t = threadIdx.x;
    if (bid < 4096) {                       // x -> xh (vec4)
        int i = bid * 1024 + t * 4;
        float4 v = *(const float4*)(x + i);
        __nv_bfloat162* dst = (__nv_bfloat162*)(g_xh + i);
        dst[0] = __floats2bfloat162_rn(v.x, v.y);
        dst[1] = __floats2bfloat162_rn(v.z, v.w);
        return;
    }
    bid -= 4096;
    if (bid < 256) {
        int o = bid * 256 + t; int n = o >> 8, k = o & 255;
        g_WqkT[o] = __float2bfloat16(Wq[k * 256 + n]);
        return;
    }
    bid -= 256;
    if (bid < 256) {
        int o = bid * 256 + t; int n = o >> 8, k = o & 255;
        g_WqkT[65536 + o] = __float2bfloat16(Wk[k * 256 + n]);
        return;
    }
    bid -= 256;
    if (bid < 128) {
        int o = bid * 256 + t; int n = o >> 8, k = o & 255;
        g_WmiT[o] = __float2bfloat16(Wm1[k * 128 + n]);
        return;
    }
    bid -= 128;
    if (bid < 256) {
        int o = bid * 256 + t; int n = o >> 8, k = o & 255;
        g_WmiT[128 * 256 + o] = __float2bfloat16(Wi1[k * 256 + n]);
        return;
    }
    bid -= 256;
    if (bid < 256) {
        int o = bid * 256 + t; int n = o >> 8, k = o & 255;
        g_Wi2T[o] = __float2bfloat16(Wi2[k * 256 + n]);
        return;
    }
    bid -= 256;
    if (bid < 128) {
        int o = bid * 256 + t; int n = o >> 8, k = o & 255;
        g_We1T[o] = __float2bfloat16(We1[k * 128 + n]);
        return;
    }
    bid -= 128;
    if (bid < 64) {
        g_awsum[bid * 256 + t] = 0.f;
        return;
    }
    bid -= 64;
    g_base[bid * 256 + t] = 0.f;            // 16 blocks
}

// ---------------- shared GEMM pipeline body --------------------------------------
__device__ __forceinline__ void gemm_core(
    const __nv_bfloat16* __restrict__ Ah, const __nv_bfloat16* __restrict__ Bt,
    int row0, uint32_t sbase, int t, int wm, int wn, int lane,
    float acc[4][4][4])
{
    const int STB = 16384;
    auto load_stage = [&](int stage, int kt) {
        uint32_t sb = sbase + stage * STB;
#pragma unroll
        for (int i = 0; i < 2; i++) {
            int c = t + i * 256;
            int row = c >> 2, ch = c & 3;
            uint32_t d = (uint32_t)((row * 4 + (ch ^ ((row >> 1) & 3))) * 16);
            cpa16(sb + d, Ah + (size_t)(row0 + row) * 256 + kt * 32 + ch * 8);
            cpa16(sb + 8192 + d, Bt + (size_t)row * 256 + kt * 32 + ch * 8);
        }
    };
    load_stage(0, 0);
    cpa_commit();
    for (int kt = 0; kt < 8; kt++) {
        int st = kt & 1;
        if (kt < 7) { load_stage(st ^ 1, kt + 1); cpa_commit(); cpa_wait1(); }
        else cpa_wait0();
        __syncthreads();
        uint32_t sb = sbase + st * STB;
#pragma unroll
        for (int kk = 0; kk < 2; kk++) {
            uint32_t ah[4][4];
#pragma unroll
            for (int mt = 0; mt < 4; mt++) {
                int row = wm * 64 + mt * 16 + (lane & 15);
                int ch = kk * 2 + (lane >> 4);
                uint32_t off = (uint32_t)((row * 4 + (ch ^ ((row >> 1) & 3))) * 16);
                ldm_x4(ah[mt], sb + off);
            }
            uint32_t bh[4][2];
#pragma unroll
            for (int p = 0; p < 2; p++) {
                int row = wn * 32 + p * 16 + (lane & 7) + 8 * (lane >> 4);
                int ch = kk * 2 + ((lane >> 3) & 1);
                uint32_t off = (uint32_t)((row * 4 + (ch ^ ((row >> 1) & 3))) * 16);
                uint32_t r4[4];
                ldm_x4(r4, sb + 8192 + off);
                bh[2 * p][0] = r4[0]; bh[2 * p][1] = r4[1];
                bh[2 * p + 1][0] = r4[2]; bh[2 * p + 1][1] = r4[3];
            }
#pragma unroll
            for (int mt = 0; mt < 4; mt++)
#pragma unroll
                for (int nt = 0; nt < 4; nt++)
                    mma_bf16(acc[mt][nt], ah[mt], bh[nt]);
        }
        __syncthreads();
    }
}

// ---------------- merged QK | M1(strengths) | I1 GEMM ----------------------------
__global__ void __launch_bounds__(256) gemm_qkmi(
    const __nv_bfloat16* __restrict__ Ah,
    const float* __restrict__ bq, const float* __restrict__ bk,
    const float* __restrict__ bm1, const float* __restrict__ bi1,
    const float* __restrict__ Wm2, const float* __restrict__ bm2)
{
    extern __shared__ char smem[];
    int t = threadIdx.x, w = t >> 5, lane = t & 31;
    int bx = blockIdx.x;
    int row0 = blockIdx.y * 128;
    int wm = w & 1, wn = w >> 1;
    int g = lane >> 2, tq = lane & 3;

    const __nv_bfloat16* Bt = (bx < 4) ? (g_WqkT + (size_t)bx * 128 * 256)
                                       : (g_WmiT + (size_t)(bx - 4) * 128 * 256);

    float acc[4][4][4];
#pragma unroll
    for (int mt = 0; mt < 4; mt++)
#pragma unroll
        for (int nt = 0; nt < 4; nt++)
#pragma unroll
            for (int r = 0; r < 4; r++) acc[mt][nt][r] = 0.f;

    gemm_core(Ah, Bt, row0, smem_u32(smem), t, wm, wn, lane, acc);

    bool head = (bx == 4);
    float* st = (float*)smem;

#pragma unroll
    for (int mt = 0; mt < 4; mt++) {
        int rl = wm * 64 + mt * 16 + g;
#pragma unroll
        for (int nt = 0; nt < 4; nt++) {
            int cl = wn * 32 + nt * 8 + 2 * tq;
#pragma unroll
            for (int half = 0; half < 2; half++) {
                int rr = row0 + rl + 8 * half;
                float v0 = acc[mt][nt][2 * half];
                float v1 = acc[mt][nt][2 * half + 1];
                if (bx < 4) {
                    int gcol = bx * 128 + cl;
                    bool isk = (gcol >= 256);
                    v0 += isk ? bk[gcol - 256] : bq[gcol];
                    v1 += isk ? bk[gcol - 255] : bq[gcol + 1];
                    *(__nv_bfloat162*)(g_qkh + (size_t)rr * 512 + gcol) =
                        __floats2bfloat162_rn(v0, v1);
                } else if (head) {
                    v0 = fmaxf(v0 + bm1[cl], 0.f);
                    v1 = fmaxf(v1 + bm1[cl + 1], 0.f);
                    st[(rl + 8 * half) * 129 + cl] = v0;
                    st[(rl + 8 * half) * 129 + cl + 1] = v1;
                } else {
                    int c2 = (bx - 5) * 128 + cl;
                    v0 = fmaxf(v0 + bi1[c2], 0.f);
                    v1 = fmaxf(v1 + bi1[c2 + 1], 0.f);
                    *(__nv_bfloat162*)(g_i1b + (size_t)rr * 256 + c2) =
                        __floats2bfloat162_rn(v0, v1);
                }
            }
        }
    }

    if (head) {
        __syncthreads();
        float wv[4];
#pragma unroll
        for (int i = 0; i < 4; i++) wv[i] = Wm2[lane + 32 * i];
        float hbv = bm2[0];
#pragma unroll
        for (int rr = w * 16; rr < w * 16 + 16; rr++) {
            float s = 0.f;
#pragma unroll
            for (int i = 0; i < 4; i++) s += wv[i] * st[rr * 129 + lane + 32 * i];
#pragma unroll
            for (int o = 16; o; o >>= 1) s += __shfl_xor_sync(0xFFFFFFFFu, s, o);
            if (lane == 0)
                g_str[row0 + rr] = 1.f / (1.f + __expf(-(s + hbv)));
        }
    }
}

// ---------------- I2+feats (MODE 2) and E1+credit (MODE 3) -----------------------
template<int MODE>
__global__ void __launch_bounds__(256) gemm_mma(
    const __nv_bfloat16* __restrict__ Ah,
    const __nv_bfloat16* __restrict__ BTh,
    const float* __restrict__ bias0,
    const float* __restrict__ hw, const float* __restrict__ hb,
    const float* __restrict__ fin,
    void* out0)
{
    extern __shared__ char smem[];
    int t = threadIdx.x, w = t >> 5, lane = t & 31;
    int row0 = blockIdx.y * 128, col0 = blockIdx.x * 128;
    int wm = w & 1, wn = w >> 1;
    int g = lane >> 2, tq = lane & 3;

    float acc[4][4][4];
#pragma unroll
    for (int mt = 0; mt < 4; mt++)
#pragma unroll
        for (int nt = 0; nt < 4; nt++)
#pragma unroll
            for (int r = 0; r < 4; r++) acc[mt][nt][r] = 0.f;

    gemm_core(Ah, BTh + (size_t)col0 * 256, row0, smem_u32(smem), t, wm, wn, lane, acc);

    float* st = (float*)smem;

#pragma unroll
    for (int mt = 0; mt < 4; mt++) {
        int rl = wm * 64 + mt * 16 + g;
#pragma unroll
        for (int nt = 0; nt < 4; nt++) {
            int cl = wn * 32 + nt * 8 + 2 * tq;
            int colb = col0 + cl;
#pragma unroll
            for (int half = 0; half < 2; half++) {
                int rr = row0 + rl + 8 * half;
                float v0 = acc[mt][nt][2 * half];
                float v1 = acc[mt][nt][2 * half + 1];
                if (MODE == 2) {
                    v0 = 0.1f * tanhf(v0 + bias0[colb]);
                    v1 = 0.1f * tanhf(v1 + bias0[colb + 1]);
                    float cmv = g_colmean[rr] * (1.f / S);
                    int bb = row0 >> 10;
                    float f0 = g_base[bb * H + colb] + v0 * cmv;
                    float f1 = g_base[bb * H + colb + 1] + v1 * cmv;
                    *(__nv_bfloat162*)((__nv_bfloat16*)out0 + (size_t)rr * 256 + colb) =
                        __floats2bfloat162_rn(f0, f1);
                } else {
                    v0 = fmaxf(v0 + bias0[colb], 0.f);
                    v1 = fmaxf(v1 + bias0[colb + 1], 0.f);
                    st[(rl + 8 * half) * 129 + cl] = v0;
                    st[(rl + 8 * half) * 129 + cl + 1] = v1;
                }
            }
        }
    }

    if (MODE == 3) {
        __syncthreads();
        float wv[4];
#pragma unroll
        for (int i = 0; i < 4; i++) wv[i] = hw[lane + 32 * i];
        float hbv = hb[0];
        int bb = row0 >> 10;
#pragma unroll
        for (int rr = w * 16; rr < w * 16 + 16; rr++) {
            float s = 0.f;
#pragma unroll
            for (int i = 0; i < 4; i++) s += wv[i] * st[rr * 129 + lane + 32 * i];
#pragma unroll
            for (int o = 16; o; o >>= 1) s += __shfl_xor_sync(0xFFFFFFFFu, s, o);
            if (lane == 0)
                ((float*)out0)[row0 + rr] = fin[bb] - (s + hbv);
        }
    }
}

// ---------------- attention column-sum (fp16 Es, ex2.f16x2, reg row sums) --------
#define ES_PITCH 1048
#define ATTN_SMEM (32768 + 4096 + 32*ES_PITCH*2 + 512 + 128)
__global__ void __launch_bounds__(256) attn_mma() {
    extern __shared__ char smem[];
    char* Kst = smem;
    char* Qh = smem + 32768;
    __half* Es = (__half*)(Qh + 4096);
    float* rpart = (float*)(smem + 32768 + 4096 + 32 * ES_PITCH * 2); // [4][32]
    float* rden = rpart + 128;

    int t = threadIdx.x, w = t >> 5, lane = t & 31;
    int qt = blockIdx.x & 31;
    int bh = blockIdx.x >> 5;
    int b = bh >> 2, h = bh & 3;
    int q0 = qt * 32;
    int wm = w & 1, wn = w >> 1;
    int g = lane >> 2, tq = lane & 3;

    uint32_t kbase = smem_u32(Kst);
    uint32_t qbase = smem_u32(Qh);

    // load Q tile (32x64), swizzled
    {
        int row = t >> 3, ch = t & 7;
        const __nv_bfloat16* sh = g_qkh + (size_t)(b * S + q0 + row) * 512 + h * DH + ch * 8;
        uint32_t d = (uint32_t)((row * 8 + (ch ^ (row & 7))) * 16);
        *(uint4*)(Qh + d) = *(const uint4*)sh;
    }

    auto load_K = [&](int stage, int kt) {
        uint32_t sbk = kbase + stage * 16384;
#pragma unroll
        for (int i = 0; i < 4; i++) {
            int c = t + i * 256;
            int j = c >> 3, ch = c & 7;
            uint32_t d = (uint32_t)((j * 8 + (ch ^ (j & 7))) * 16);
            size_t src = (size_t)(b * S + kt * 128 + j) * 512 + 256 + h * DH + ch * 8;
            cpa16(sbk + d, g_qkh + src);
        }
    };

    load_K(0, 0);
    cpa_commit();

    float rsum0 = 0.f, rsum1 = 0.f;
    const float CEXP = 0.125f * 1.44269504f;

    for (int kt = 0; kt < 8; kt++) {
        int stg = kt & 1;
        if (kt < 7) { load_K(stg ^ 1, kt + 1); cpa_commit(); cpa_wait1(); }
        else cpa_wait0();
        __syncthreads();
        uint32_t sbk = kbase + stg * 16384;

        float acc[4][4];
#pragma unroll
        for (int nt = 0; nt < 4; nt++)
#pragma unroll
            for (int r = 0; r < 4; r++) acc[nt][r] = 0.f;

#pragma unroll
        for (int d16 = 0; d16 < 4; d16++) {
            uint32_t ah[4];
            {
                int row = wm * 16 + (lane & 15);
                int ch = d16 * 2 + (lane >> 4);
                uint32_t off = (uint32_t)((row * 8 + (ch ^ (row & 7))) * 16);
                ldm_x4(ah, qbase + off);
            }
            uint32_t bh2[4][2];
#pragma unroll
            for (int p = 0; p < 2; p++) {
                int j = wn * 32 + p * 16 + (lane & 7) + 8 * (lane >> 4);
                int ch = d16 * 2 + ((lane >> 3) & 1);
                uint32_t off = (uint32_t)((j * 8 + (ch ^ (j & 7))) * 16);
                uint32_t r4[4];
                ldm_x4(r4, sbk + off);
                bh2[2 * p][0] = r4[0]; bh2[2 * p][1] = r4[1];
                bh2[2 * p + 1][0] = r4[2]; bh2[2 * p + 1][1] = r4[3];
            }
#pragma unroll
            for (int nt = 0; nt < 4; nt++) mma_bf16(acc[nt], ah, bh2[nt]);
        }
#pragma unroll
        for (int nt = 0; nt < 4; nt++) {
            int colb = kt * 128 + wn * 32 + nt * 8 + 2 * tq;
            uint32_t e0 = h2_ex2(h2_pack(acc[nt][0] * CEXP, acc[nt][1] * CEXP));
            uint32_t e1 = h2_ex2(h2_pack(acc[nt][2] * CEXP, acc[nt][3] * CEXP));
            float2 f0 = h2_unpack(e0);
            float2 f1 = h2_unpack(e1);
            rsum0 += f0.x + f0.y;
            rsum1 += f1.x + f1.y;
            int r0 = wm * 16 + g;
            *(uint32_t*)&Es[r0 * ES_PITCH + colb] = e0;
            *(uint32_t*)&Es[(r0 + 8) * ES_PITCH + colb] = e1;
        }
        __syncthreads();
    }

    rsum0 += __shfl_xor_sync(0xFFFFFFFFu, rsum0, 1);
    rsum0 += __shfl_xor_sync(0xFFFFFFFFu, rsum0, 2);
    rsum1 += __shfl_xor_sync(0xFFFFFFFFu, rsum1, 1);
    rsum1 += __shfl_xor_sync(0xFFFFFFFFu, rsum1, 2);
    if (tq == 0) {
        rpart[wn * 32 + wm * 16 + g] = rsum0;
        rpart[wn * 32 + wm * 16 + g + 8] = rsum1;
    }
    __syncthreads();
    if (t < 32)
        rden[t] = 1.f / (rpart[t] + rpart[32 + t] + rpart[64 + t] + rpart[96 + t]);
    __syncthreads();

#pragma unroll
    for (int jj = 0; jj < 2; jj++) {
        int j2 = t + jj * 256;
        float sx = 0.f, sy = 0.f;
#pragma unroll
        for (int r = 0; r < 32; r++) {
            float2 e = __half22float2(((__half2*)(Es + r * ES_PITCH))[j2]);
            float rd = rden[r];
            sx += e.x * rd;
            sy += e.y * rd;
        }
        atomicAdd(&g_awsum[b * S + 2 * j2], sx);
        atomicAdd(&g_awsum[b * S + 2 * j2 + 1], sy);
    }
}

// ---------------- colmean (redundant scan) + parallel base -----------------------
// grid (B, 8): every block scans batch b; block y=sc sums s-chunk sc for base.
__global__ void __launch_bounds__(1024) colmean_base_k() {
    __shared__ float s0[1024], s1[1024], cmb[1024], bacc[4][256];
    int b = blockIdx.x, sc = blockIdx.y, j = threadIdx.x;
    s0[j] = g_str[b * S + j];
    __syncthreads();
    float* cur = s0; float* nxt = s1;
#pragma unroll
    for (int off = 1; off < 1024; off <<= 1) {
        float v = cur[j];
        if (j + off < 1024) v += cur[j + off];
        __syncthreads();
        nxt[j] = v;
        __syncthreads();
        float* tmp = cur; cur = nxt; nxt = tmp;
    }
    float awm = g_awsum[b * S + j] * (1.f / (NH * S));
    float cmv = awm * cur[j] * (1.f / S);
    if (sc == 0) {
        g_awm[b * S + j] = awm;
        g_colmean[b * S + j] = cmv;
    }
    cmb[j] = cmv;
    __syncthreads();
    // base partial for s in [sc*128, sc*128+128): 4 s-subgroups x 256 h
    int h = j & 255, sg = j >> 8;
    const __nv_bfloat16* xb = g_xh + (size_t)b * S * H;
    int sbeg = sc * 128 + sg * 32;
    float a = 0.f;
    for (int s = sbeg; s < sbeg + 32; s++)
        a += __bfloat162float(xb[(size_t)s * H + h]) * cmb[s];
    bacc[sg][h] = a;
    __syncthreads();
    if (j < 256)
        atomicAdd(&g_base[b * H + j],
                  (bacc[0][j] + bacc[1][j] + bacc[2][j] + bacc[3][j]) * (1.f / S));
}

// ---------------- cm output ----------------
__global__ void cm_k(float* __restrict__ out) {
    int bi = blockIdx.x;
    int b = bi >> 10, i = bi & 1023;
    float stv = g_str[bi];
    const float4* aw = (const float4*)(g_awm + b * S);
    float4* o = (float4*)(out + (size_t)bi * S);
    int j4 = threadIdx.x;
    float4 a = aw[j4];
    int j = j4 * 4;
    float4 v;
    v.x = (i >= j)     ? a.x * stv : 0.f;
    v.y = (i >= j + 1) ? a.y * stv : 0.f;
    v.z = (i >= j + 2) ? a.z * stv : 0.f;
    v.w = (i >= j + 3) ? a.w * stv : 0.f;
    o[j4] = v;
}

// ---------------- launch ----------------
extern "C" void kernel_launch(void* const* d_in, const int* in_sizes, int n_in,
                              void* d_out, int out_size) {
    const float* x    = (const float*)d_in[0];
    const float* fin  = (const float*)d_in[1];
    const float* Wq   = (const float*)d_in[3];
    const float* bq   = (const float*)d_in[4];
    const float* Wk   = (const float*)d_in[5];
    const float* bk   = (const float*)d_in[6];
    const float* Wm1  = (const float*)d_in[7];
    const float* bm1  = (const float*)d_in[8];
    const float* Wm2  = (const float*)d_in[9];
    const float* bm2  = (const float*)d_in[10];
    const float* Wi1  = (const float*)d_in[11];
    const float* bi1  = (const float*)d_in[12];
    const float* Wi2  = (const float*)d_in[13];
    const float* bi2  = (const float*)d_in[14];
    const float* We1  = (const float*)d_in[15];
    const float* be1  = (const float*)d_in[16];
    const float* We2  = (const float*)d_in[17];
    const float* be2  = (const float*)d_in[18];
    float* out = (float*)d_out;

    __nv_bfloat16 *pxh, *pWi2T, *pWe1T, *pi1b, *pfb;
    cudaGetSymbolAddress((void**)&pxh, g_xh);
    cudaGetSymbolAddress((void**)&pWi2T, g_Wi2T);
    cudaGetSymbolAddress((void**)&pWe1T, g_We1T);
    cudaGetSymbolAddress((void**)&pi1b, g_i1b);
    cudaGetSymbolAddress((void**)&pfb, g_fb);

    const int SM_1P = 32768, SM_HEAD = 66048;
    cudaFuncSetAttribute(gemm_qkmi, cudaFuncAttributeMaxDynamicSharedMemorySize, SM_HEAD);
    cudaFuncSetAttribute(gemm_mma<2>, cudaFuncAttributeMaxDynamicSharedMemorySize, SM_1P);
    cudaFuncSetAttribute(gemm_mma<3>, cudaFuncAttributeMaxDynamicSharedMemorySize, SM_HEAD);
    cudaFuncSetAttribute(attn_mma, cudaFuncAttributeMaxDynamicSharedMemorySize, ATTN_SMEM);

    // 1. prep (conversions + transposes + zero awsum/base)
    prep_k<<<5456, 256>>>(x, Wq, Wk, Wm1, Wi1, Wi2, We1);

    // 2. merged QK | strengths | I1
    gemm_qkmi<<<dim3(7,128), 256, SM_HEAD>>>(pxh, bq, bk, bm1, bi1, Wm2, bm2);

    // 3. attention column sums
    attn_mma<<<B*NH*32, 256, ATTN_SMEM>>>();

    // 4. colmean (scan) + base (parallel, 128 blocks)
    colmean_base_k<<<dim3(B,8), 1024>>>();

    // 5. I2 + fused feats
    gemm_mma<2><<<dim3(2,128), 256, SM_1P>>>(pi1b, pWi2T, bi2,
                                             nullptr, nullptr, nullptr, pfb);
    // 6. E1 + fused credit head -> out[0 : B*S]
    gemm_mma<3><<<dim3(1,128), 256, SM_HEAD>>>(pfb, pWe1T, be1,
                                               We2, be2, fin, out);
    // 7. cm -> out[B*S : ]
    cm_k<<<MROWS, 256>>>(out + B*S);
}

// round 10
// speedup vs baseline: 1.3188x; 1.0613x over previous
#include <cuda_runtime.h>
#include <cuda_bf16.h>
#include <cuda_fp16.h>
#include <math.h>
#include <stdint.h>

#define B 16
#define S 1024
#define H 256
#define NH 4
#define DH 64
#define H2 128
#define MROWS (B*S)   // 16384
#define CEXP (0.125f * 1.44269504f)

// ---------------- scratch (static device globals) ----------------
__device__ __align__(16) __nv_bfloat16 g_xh[MROWS*H];
__device__ __align__(16) __nv_bfloat16 g_WqkT[512*H];                    // [Wq|Wk]^T
__device__ __align__(16) __nv_bfloat16 g_WmiT[384*H];                    // [Wm1|Wi1]^T
__device__ __align__(16) __nv_bfloat16 g_Wi2T[H*H];
__device__ __align__(16) __nv_bfloat16 g_We1T[H2*H];
__device__ __align__(16) __nv_bfloat16 g_qkh[MROWS*512];                 // packed q|k bf16 (q pre-scaled by CEXP)
__device__ __align__(16) __nv_bfloat16 g_i1b[MROWS*H];
__device__ __align__(16) __nv_bfloat16 g_fb[MROWS*H];
__device__ float g_str[B*S];
__device__ float g_awsum[B*S];
__device__ float g_awm[B*S];
__device__ float g_colmean[B*S];
__device__ float g_base[B*H];

// ---------------- PTX helpers ----------------
__device__ __forceinline__ uint32_t smem_u32(const void* p) {
    return (uint32_t)__cvta_generic_to_shared(p);
}
__device__ __forceinline__ void ldm_x4(uint32_t* r, uint32_t a) {
    asm volatile("ldmatrix.sync.aligned.m8n8.x4.shared.b16 {%0,%1,%2,%3}, [%4];"
        : "=r"(r[0]), "=r"(r[1]), "=r"(r[2]), "=r"(r[3]) : "r"(a));
}
__device__ __forceinline__ void mma_bf16(float* c, const uint32_t* a, const uint32_t* b) {
    asm volatile(
        "mma.sync.aligned.m16n8k16.row.col.f32.bf16.bf16.f32 "
        "{%0,%1,%2,%3},{%4,%5,%6,%7},{%8,%9},{%0,%1,%2,%3};"
        : "+f"(c[0]), "+f"(c[1]), "+f"(c[2]), "+f"(c[3])
        : "r"(a[0]), "r"(a[1]), "r"(a[2]), "r"(a[3]), "r"(b[0]), "r"(b[1]));
}
__device__ __forceinline__ void cpa16(uint32_t dst, const void* src) {
    asm volatile("cp.async.cg.shared.global [%0], [%1], 16;" :: "r"(dst), "l"(src));
}
__device__ __forceinline__ void cpa_commit() { asm volatile("cp.async.commit_group;"); }
__device__ __forceinline__ void cpa_wait1() { asm volatile("cp.async.wait_group 1;"); }
__device__ __forceinline__ void cpa_wait0() { asm volatile("cp.async.wait_group 0;"); }

__device__ __forceinline__ uint32_t h2_ex2(uint32_t x) {
    uint32_t r; asm("ex2.approx.f16x2 %0, %1;" : "=r"(r) : "r"(x)); return r;
}
__device__ __forceinline__ uint32_t h2_pack(float a, float b) {
    __half2 h = __floats2half2_rn(a, b);
    return *reinterpret_cast<uint32_t*>(&h);
}
__device__ __forceinline__ float2 h2_unpack(uint32_t u) {
    return __half22float2(*reinterpret_cast<__half2*>(&u));
}

// ---------------- fused prep: x->bf16, weight transposes, zero awsum+base --------
__global__ void prep_k(const float* __restrict__ x,
                       const float* __restrict__ Wq, const float* __restrict__ Wk,
                       const float* __restrict__ Wm1, const float* __restrict__ Wi1,
                       const float* __restrict__ Wi2, const float* __restrict__ We1) {
    int bid = blockIdx.x, t = threadIdx.x;
    if (bid < 4096) {                       // x -> xh (vec4)
        int i = bid * 1024 + t * 4;
        float4 v = *(const float4*)(x + i);
        __nv_bfloat162* dst = (__nv_bfloat162*)(g_xh + i);
        dst[0] = __floats2bfloat162_rn(v.x, v.y);
        dst[1] = __floats2bfloat162_rn(v.z, v.w);
        return;
    }
    bid -= 4096;
    if (bid < 256) {
        int o = bid * 256 + t; int n = o >> 8, k = o & 255;
        g_WqkT[o] = __float2bfloat16(Wq[k * 256 + n]);
        return;
    }
    bid -= 256;
    if (bid < 256) {
        int o = bid * 256 + t; int n = o >> 8, k = o & 255;
        g_WqkT[65536 + o] = __float2bfloat16(Wk[k * 256 + n]);
        return;
    }
    bid -= 256;
    if (bid < 128) {
        int o = bid * 256 + t; int n = o >> 8, k = o & 255;
        g_WmiT[o] = __float2bfloat16(Wm1[k * 128 + n]);
        return;
    }
    bid -= 128;
    if (bid < 256) {
        int o = bid * 256 + t; int n = o >> 8, k = o & 255;
        g_WmiT[128 * 256 + o] = __float2bfloat16(Wi1[k * 256 + n]);
        return;
    }
    bid -= 256;
    if (bid < 256) {
        int o = bid * 256 + t; int n = o >> 8, k = o & 255;
        g_Wi2T[o] = __float2bfloat16(Wi2[k * 256 + n]);
        return;
    }
    bid -= 256;
    if (bid < 128) {
        int o = bid * 256 + t; int n = o >> 8, k = o & 255;
        g_We1T[o] = __float2bfloat16(We1[k * 128 + n]);
        return;
    }
    bid -= 128;
    if (bid < 64) {
        g_awsum[bid * 256 + t] = 0.f;
        return;
    }
    bid -= 64;
    g_base[bid * 256 + t] = 0.f;
}

// ---------------- shared GEMM pipeline body --------------------------------------
__device__ __forceinline__ void gemm_core(
    const __nv_bfloat16* __restrict__ Ah, const __nv_bfloat16* __restrict__ Bt,
    int row0, uint32_t sbase, int t, int wm, int wn, int lane,
    float acc[4][4][4])
{
    const int STB = 16384;
    auto load_stage = [&](int stage, int kt) {
        uint32_t sb = sbase + stage * STB;
#pragma unroll
        for (int i = 0; i < 2; i++) {
            int c = t + i * 256;
            int row = c >> 2, ch = c & 3;
            uint32_t d = (uint32_t)((row * 4 + (ch ^ ((row >> 1) & 3))) * 16);
            cpa16(sb + d, Ah + (size_t)(row0 + row) * 256 + kt * 32 + ch * 8);
            cpa16(sb + 8192 + d, Bt + (size_t)row * 256 + kt * 32 + ch * 8);
        }
    };
    load_stage(0, 0);
    cpa_commit();
    for (int kt = 0; kt < 8; kt++) {
        int st = kt & 1;
        if (kt < 7) { load_stage(st ^ 1, kt + 1); cpa_commit(); cpa_wait1(); }
        else cpa_wait0();
        __syncthreads();
        uint32_t sb = sbase + st * STB;
#pragma unroll
        for (int kk = 0; kk < 2; kk++) {
            uint32_t ah[4][4];
#pragma unroll
            for (int mt = 0; mt < 4; mt++) {
                int row = wm * 64 + mt * 16 + (lane & 15);
                int ch = kk * 2 + (lane >> 4);
                uint32_t off = (uint32_t)((row * 4 + (ch ^ ((row >> 1) & 3))) * 16);
                ldm_x4(ah[mt], sb + off);
            }
            uint32_t bh[4][2];
#pragma unroll
            for (int p = 0; p < 2; p++) {
                int row = wn * 32 + p * 16 + (lane & 7) + 8 * (lane >> 4);
                int ch = kk * 2 + ((lane >> 3) & 1);
                uint32_t off = (uint32_t)((row * 4 + (ch ^ ((row >> 1) & 3))) * 16);
                uint32_t r4[4];
                ldm_x4(r4, sb + 8192 + off);
                bh[2 * p][0] = r4[0]; bh[2 * p][1] = r4[1];
                bh[2 * p + 1][0] = r4[2]; bh[2 * p + 1][1] = r4[3];
            }
#pragma unroll
            for (int mt = 0; mt < 4; mt++)
#pragma unroll
                for (int nt = 0; nt < 4; nt++)
                    mma_bf16(acc[mt][nt], ah[mt], bh[nt]);
        }
        __syncthreads();
    }
}

// ---------------- merged QK | M1(strengths) | I1 GEMM ----------------------------
__global__ void __launch_bounds__(256) gemm_qkmi(
    const __nv_bfloat16* __restrict__ Ah,
    const float* __restrict__ bq, const float* __restrict__ bk,
    const float* __restrict__ bm1, const float* __restrict__ bi1,
    const float* __restrict__ Wm2, const float* __restrict__ bm2)
{
    extern __shared__ char smem[];
    int t = threadIdx.x, w = t >> 5, lane = t & 31;
    int bx = blockIdx.x;
    int row0 = blockIdx.y * 128;
    int wm = w & 1, wn = w >> 1;
    int g = lane >> 2, tq = lane & 3;

    const __nv_bfloat16* Bt = (bx < 4) ? (g_WqkT + (size_t)bx * 128 * 256)
                                       : (g_WmiT + (size_t)(bx - 4) * 128 * 256);

    float acc[4][4][4];
#pragma unroll
    for (int mt = 0; mt < 4; mt++)
#pragma unroll
        for (int nt = 0; nt < 4; nt++)
#pragma unroll
            for (int r = 0; r < 4; r++) acc[mt][nt][r] = 0.f;

    gemm_core(Ah, Bt, row0, smem_u32(smem), t, wm, wn, lane, acc);

    bool head = (bx == 4);
    float* st = (float*)smem;

#pragma unroll
    for (int mt = 0; mt < 4; mt++) {
        int rl = wm * 64 + mt * 16 + g;
#pragma unroll
        for (int nt = 0; nt < 4; nt++) {
            int cl = wn * 32 + nt * 8 + 2 * tq;
#pragma unroll
            for (int half = 0; half < 2; half++) {
                int rr = row0 + rl + 8 * half;
                float v0 = acc[mt][nt][2 * half];
                float v1 = acc[mt][nt][2 * half + 1];
                if (bx < 4) {
                    int gcol = bx * 128 + cl;
                    bool isk = (gcol >= 256);
                    v0 += isk ? bk[gcol - 256] : bq[gcol];
                    v1 += isk ? bk[gcol - 255] : bq[gcol + 1];
                    if (!isk) { v0 *= CEXP; v1 *= CEXP; }   // pre-scale q for ex2
                    *(__nv_bfloat162*)(g_qkh + (size_t)rr * 512 + gcol) =
                        __floats2bfloat162_rn(v0, v1);
                } else if (head) {
                    v0 = fmaxf(v0 + bm1[cl], 0.f);
                    v1 = fmaxf(v1 + bm1[cl + 1], 0.f);
                    st[(rl + 8 * half) * 129 + cl] = v0;
                    st[(rl + 8 * half) * 129 + cl + 1] = v1;
                } else {
                    int c2 = (bx - 5) * 128 + cl;
                    v0 = fmaxf(v0 + bi1[c2], 0.f);
                    v1 = fmaxf(v1 + bi1[c2 + 1], 0.f);
                    *(__nv_bfloat162*)(g_i1b + (size_t)rr * 256 + c2) =
                        __floats2bfloat162_rn(v0, v1);
                }
            }
        }
    }

    if (head) {
        __syncthreads();
        float wv[4];
#pragma unroll
        for (int i = 0; i < 4; i++) wv[i] = Wm2[lane + 32 * i];
        float hbv = bm2[0];
#pragma unroll
        for (int rr = w * 16; rr < w * 16 + 16; rr++) {
            float s = 0.f;
#pragma unroll
            for (int i = 0; i < 4; i++) s += wv[i] * st[rr * 129 + lane + 32 * i];
#pragma unroll
            for (int o = 16; o; o >>= 1) s += __shfl_xor_sync(0xFFFFFFFFu, s, o);
            if (lane == 0)
                g_str[row0 + rr] = 1.f / (1.f + __expf(-(s + hbv)));
        }
    }
}

// ---------------- I2+feats (MODE 2, + fused cm writer blocks) and E1+credit ------
template<int MODE>
__global__ void __launch_bounds__(256) gemm_mma(
    const __nv_bfloat16* __restrict__ Ah,
    const __nv_bfloat16* __restrict__ BTh,
    const float* __restrict__ bias0,
    const float* __restrict__ hw, const float* __restrict__ hb,
    const float* __restrict__ fin,
    void* out0, float* __restrict__ cmout)
{
    extern __shared__ char smem[];
    int t = threadIdx.x, w = t >> 5, lane = t & 31;

    // cm-writer blocks (MODE 2, bx >= 2): stream cm output, no GEMM
    if (MODE == 2 && blockIdx.x >= 2) {
        int blk = (blockIdx.x - 2) * 128 + blockIdx.y;   // 0..255
        int j4 = t;                                       // float4 col slot
        for (int r = 0; r < 64; r++) {
            int bi = blk * 64 + r;
            int b = bi >> 10, i = bi & 1023;
            float stv = g_str[bi];
            float4 a = ((const float4*)(g_awm + b * S))[j4];
            int j = j4 * 4;
            float4 v;
            v.x = (i >= j)     ? a.x * stv : 0.f;
            v.y = (i >= j + 1) ? a.y * stv : 0.f;
            v.z = (i >= j + 2) ? a.z * stv : 0.f;
            v.w = (i >= j + 3) ? a.w * stv : 0.f;
            ((float4*)(cmout + (size_t)bi * S))[j4] = v;
        }
        return;
    }

    int row0 = blockIdx.y * 128, col0 = blockIdx.x * 128;
    int wm = w & 1, wn = w >> 1;
    int g = lane >> 2, tq = lane & 3;

    float acc[4][4][4];
#pragma unroll
    for (int mt = 0; mt < 4; mt++)
#pragma unroll
        for (int nt = 0; nt < 4; nt++)
#pragma unroll
            for (int r = 0; r < 4; r++) acc[mt][nt][r] = 0.f;

    gemm_core(Ah, BTh + (size_t)col0 * 256, row0, smem_u32(smem), t, wm, wn, lane, acc);

    float* st = (float*)smem;

#pragma unroll
    for (int mt = 0; mt < 4; mt++) {
        int rl = wm * 64 + mt * 16 + g;
#pragma unroll
        for (int nt = 0; nt < 4; nt++) {
            int cl = wn * 32 + nt * 8 + 2 * tq;
            int colb = col0 + cl;
#pragma unroll
            for (int half = 0; half < 2; half++) {
                int rr = row0 + rl + 8 * half;
                float v0 = acc[mt][nt][2 * half];
                float v1 = acc[mt][nt][2 * half + 1];
                if (MODE == 2) {
                    v0 = 0.1f * tanhf(v0 + bias0[colb]);
                    v1 = 0.1f * tanhf(v1 + bias0[colb + 1]);
                    float cmv = g_colmean[rr] * (1.f / S);
                    int bb = row0 >> 10;
                    float f0 = g_base[bb * H + colb] + v0 * cmv;
                    float f1 = g_base[bb * H + colb + 1] + v1 * cmv;
                    *(__nv_bfloat162*)((__nv_bfloat16*)out0 + (size_t)rr * 256 + colb) =
                        __floats2bfloat162_rn(f0, f1);
                } else {
                    v0 = fmaxf(v0 + bias0[colb], 0.f);
                    v1 = fmaxf(v1 + bias0[colb + 1], 0.f);
                    st[(rl + 8 * half) * 129 + cl] = v0;
                    st[(rl + 8 * half) * 129 + cl + 1] = v1;
                }
            }
        }
    }

    if (MODE == 3) {
        __syncthreads();
        float wv[4];
#pragma unroll
        for (int i = 0; i < 4; i++) wv[i] = hw[lane + 32 * i];
        float hbv = hb[0];
        int bb = row0 >> 10;
#pragma unroll
        for (int rr = w * 16; rr < w * 16 + 16; rr++) {
            float s = 0.f;
#pragma unroll
            for (int i = 0; i < 4; i++) s += wv[i] * st[rr * 129 + lane + 32 * i];
#pragma unroll
            for (int o = 16; o; o >>= 1) s += __shfl_xor_sync(0xFFFFFFFFu, s, o);
            if (lane == 0)
                ((float*)out0)[row0 + rr] = fin[bb] - (s + hbv);
        }
    }
}

// ---------------- attention column-sum (fp16 Es, hoisted Q, pre-scaled q) --------
#define ES_PITCH 1048
#define ATTN_SMEM (32768 + 4096 + 32*ES_PITCH*2 + 512 + 128)
__global__ void __launch_bounds__(256) attn_mma() {
    extern __shared__ char smem[];
    char* Kst = smem;
    char* Qh = smem + 32768;
    __half* Es = (__half*)(Qh + 4096);
    float* rpart = (float*)(smem + 32768 + 4096 + 32 * ES_PITCH * 2); // [4][32]
    float* rden = rpart + 128;

    int t = threadIdx.x, w = t >> 5, lane = t & 31;
    int qt = blockIdx.x & 31;
    int bh = blockIdx.x >> 5;
    int b = bh >> 2, h = bh & 3;
    int q0 = qt * 32;
    int wm = w & 1, wn = w >> 1;
    int g = lane >> 2, tq = lane & 3;

    uint32_t kbase = smem_u32(Kst);
    uint32_t qbase = smem_u32(Qh);

    // load Q tile (32x64), swizzled
    {
        int row = t >> 3, ch = t & 7;
        const __nv_bfloat16* sh = g_qkh + (size_t)(b * S + q0 + row) * 512 + h * DH + ch * 8;
        uint32_t d = (uint32_t)((row * 8 + (ch ^ (row & 7))) * 16);
        *(uint4*)(Qh + d) = *(const uint4*)sh;
    }

    auto load_K = [&](int stage, int kt) {
        uint32_t sbk = kbase + stage * 16384;
#pragma unroll
        for (int i = 0; i < 4; i++) {
            int c = t + i * 256;
            int j = c >> 3, ch = c & 7;
            uint32_t d = (uint32_t)((j * 8 + (ch ^ (j & 7))) * 16);
            size_t src = (size_t)(b * S + kt * 128 + j) * 512 + 256 + h * DH + ch * 8;
            cpa16(sbk + d, g_qkh + src);
        }
    };

    load_K(0, 0);
    cpa_commit();
    __syncthreads();                 // Q STS visible

    // hoist Q fragments (loop-invariant)
    uint32_t aq[4][4];
#pragma unroll
    for (int d16 = 0; d16 < 4; d16++) {
        int row = wm * 16 + (lane & 15);
        int ch = d16 * 2 + (lane >> 4);
        uint32_t off = (uint32_t)((row * 8 + (ch ^ (row & 7))) * 16);
        ldm_x4(aq[d16], qbase + off);
    }

    float rsum0 = 0.f, rsum1 = 0.f;

    for (int kt = 0; kt < 8; kt++) {
        int stg = kt & 1;
        if (kt < 7) { load_K(stg ^ 1, kt + 1); cpa_commit(); cpa_wait1(); }
        else cpa_wait0();
        __syncthreads();
        uint32_t sbk = kbase + stg * 16384;

        float acc[4][4];
#pragma unroll
        for (int nt = 0; nt < 4; nt++)
#pragma unroll
            for (int r = 0; r < 4; r++) acc[nt][r] = 0.f;

#pragma unroll
        for (int d16 = 0; d16 < 4; d16++) {
            uint32_t bh2[4][2];
#pragma unroll
            for (int p = 0; p < 2; p++) {
                int j = wn * 32 + p * 16 + (lane & 7) + 8 * (lane >> 4);
                int ch = d16 * 2 + ((lane >> 3) & 1);
                uint32_t off = (uint32_t)((j * 8 + (ch ^ (j & 7))) * 16);
                uint32_t r4[4];
                ldm_x4(r4, sbk + off);
                bh2[2 * p][0] = r4[0]; bh2[2 * p][1] = r4[1];
                bh2[2 * p + 1][0] = r4[2]; bh2[2 * p + 1][1] = r4[3];
            }
#pragma unroll
            for (int nt = 0; nt < 4; nt++) mma_bf16(acc[nt], aq[d16], bh2[nt]);
        }
#pragma unroll
        for (int nt = 0; nt < 4; nt++) {
            int colb = kt * 128 + wn * 32 + nt * 8 + 2 * tq;
            uint32_t e0 = h2_ex2(h2_pack(acc[nt][0], acc[nt][1]));   // q pre-scaled
            uint32_t e1 = h2_ex2(h2_pack(acc[nt][2], acc[nt][3]));
            float2 f0 = h2_unpack(e0);
            float2 f1 = h2_unpack(e1);
            rsum0 += f0.x + f0.y;
            rsum1 += f1.x + f1.y;
            int r0 = wm * 16 + g;
            *(uint32_t*)&Es[r0 * ES_PITCH + colb] = e0;
            *(uint32_t*)&Es[(r0 + 8) * ES_PITCH + colb] = e1;
        }
        __syncthreads();
    }

    rsum0 += __shfl_xor_sync(0xFFFFFFFFu, rsum0, 1);
    rsum0 += __shfl_xor_sync(0xFFFFFFFFu, rsum0, 2);
    rsum1 += __shfl_xor_sync(0xFFFFFFFFu, rsum1, 1);
    rsum1 += __shfl_xor_sync(0xFFFFFFFFu, rsum1, 2);
    if (tq == 0) {
        rpart[wn * 32 + wm * 16 + g] = rsum0;
        rpart[wn * 32 + wm * 16 + g + 8] = rsum1;
    }
    __syncthreads();
    if (t < 32)
        rden[t] = 1.f / (rpart[t] + rpart[32 + t] + rpart[64 + t] + rpart[96 + t]);
    __syncthreads();

#pragma unroll
    for (int jj = 0; jj < 2; jj++) {
        int j2 = t + jj * 256;
        float sx = 0.f, sy = 0.f;
#pragma unroll
        for (int r = 0; r < 32; r++) {
            float2 e = __half22float2(((__half2*)(Es + r * ES_PITCH))[j2]);
            float rd = rden[r];
            sx += e.x * rd;
            sy += e.y * rd;
        }
        atomicAdd(&g_awsum[b * S + 2 * j2], sx);
        atomicAdd(&g_awsum[b * S + 2 * j2 + 1], sy);
    }
}

// ---------------- colmean (redundant scan) + parallel base -----------------------
__global__ void __launch_bounds__(1024) colmean_base_k() {
    __shared__ float s0[1024], s1[1024], cmb[1024], bacc[4][256];
    int b = blockIdx.x, sc = blockIdx.y, j = threadIdx.x;
    s0[j] = g_str[b * S + j];
    __syncthreads();
    float* cur = s0; float* nxt = s1;
#pragma unroll
    for (int off = 1; off < 1024; off <<= 1) {
        float v = cur[j];
        if (j + off < 1024) v += cur[j + off];
        __syncthreads();
        nxt[j] = v;
        __syncthreads();
        float* tmp = cur; cur = nxt; nxt = tmp;
    }
    float awm = g_awsum[b * S + j] * (1.f / (NH * S));
    float cmv = awm * cur[j] * (1.f / S);
    if (sc == 0) {
        g_awm[b * S + j] = awm;
        g_colmean[b * S + j] = cmv;
    }
    cmb[j] = cmv;
    __syncthreads();
    int h = j & 255, sg = j >> 8;
    const __nv_bfloat16* xb = g_xh + (size_t)b * S * H;
    int sbeg = sc * 128 + sg * 32;
    float a = 0.f;
    for (int s = sbeg; s < sbeg + 32; s++)
        a += __bfloat162float(xb[(size_t)s * H + h]) * cmb[s];
    bacc[sg][h] = a;
    __syncthreads();
    if (j < 256)
        atomicAdd(&g_base[b * H + j],
                  (bacc[0][j] + bacc[1][j] + bacc[2][j] + bacc[3][j]) * (1.f / S));
}

// ---------------- launch ----------------
extern "C" void kernel_launch(void* const* d_in, const int* in_sizes, int n_in,
                              void* d_out, int out_size) {
    const float* x    = (const float*)d_in[0];
    const float* fin  = (const float*)d_in[1];
    const float* Wq   = (const float*)d_in[3];
    const float* bq   = (const float*)d_in[4];
    const float* Wk   = (const float*)d_in[5];
    const float* bk   = (const float*)d_in[6];
    const float* Wm1  = (const float*)d_in[7];
    const float* bm1  = (const float*)d_in[8];
    const float* Wm2  = (const float*)d_in[9];
    const float* bm2  = (const float*)d_in[10];
    const float* Wi1  = (const float*)d_in[11];
    const float* bi1  = (const float*)d_in[12];
    const float* Wi2  = (const float*)d_in[13];
    const float* bi2  = (const float*)d_in[14];
    const float* We1  = (const float*)d_in[15];
    const float* be1  = (const float*)d_in[16];
    const float* We2  = (const float*)d_in[17];
    const float* be2  = (const float*)d_in[18];
    float* out = (float*)d_out;

    __nv_bfloat16 *pxh, *pWi2T, *pWe1T, *pi1b, *pfb;
    cudaGetSymbolAddress((void**)&pxh, g_xh);
    cudaGetSymbolAddress((void**)&pWi2T, g_Wi2T);
    cudaGetSymbolAddress((void**)&pWe1T, g_We1T);
    cudaGetSymbolAddress((void**)&pi1b, g_i1b);
    cudaGetSymbolAddress((void**)&pfb, g_fb);

    const int SM_1P = 32768, SM_HEAD = 66048;
    cudaFuncSetAttribute(gemm_qkmi, cudaFuncAttributeMaxDynamicSharedMemorySize, SM_HEAD);
    cudaFuncSetAttribute(gemm_mma<2>, cudaFuncAttributeMaxDynamicSharedMemorySize, SM_1P);
    cudaFuncSetAttribute(gemm_mma<3>, cudaFuncAttributeMaxDynamicSharedMemorySize, SM_HEAD);
    cudaFuncSetAttribute(attn_mma, cudaFuncAttributeMaxDynamicSharedMemorySize, ATTN_SMEM);

    // 1. prep
    prep_k<<<5456, 256>>>(x, Wq, Wk, Wm1, Wi1, Wi2, We1);

    // 2. merged QK | strengths | I1
    gemm_qkmi<<<dim3(7,128), 256, SM_HEAD>>>(pxh, bq, bk, bm1, bi1, Wm2, bm2);

    // 3. attention column sums
    attn_mma<<<B*NH*32, 256, ATTN_SMEM>>>();

    // 4. colmean (scan) + base
    colmean_base_k<<<dim3(B,8), 1024>>>();

    // 5. I2 + fused feats, plus cm-writer blocks (bx>=2) -> out[B*S:]
    gemm_mma<2><<<dim3(4,128), 256, SM_1P>>>(pi1b, pWi2T, bi2,
                                             nullptr, nullptr, nullptr, pfb, out + B*S);
    // 6. E1 + fused credit head -> out[0 : B*S]
    gemm_mma<3><<<dim3(1,128), 256, SM_HEAD>>>(pfb, pWe1T, be1,
                                               We2, be2, fin, out, nullptr);
}

// round 11
// speedup vs baseline: 1.3642x; 1.0344x over previous
#include <cuda_runtime.h>
#include <cuda_bf16.h>
#include <cuda_fp16.h>
#include <math.h>
#include <stdint.h>

#define B 16
#define S 1024
#define H 256
#define NH 4
#define DH 64
#define H2 128
#define MROWS (B*S)   // 16384
#define CEXP (0.125f * 1.44269504f)

// ---------------- scratch (static device globals) ----------------
__device__ __align__(16) __nv_bfloat16 g_xh[MROWS*H];
__device__ __align__(16) __nv_bfloat16 g_WqkT[512*H];                    // [Wq|Wk]^T
__device__ __align__(16) __nv_bfloat16 g_WmiT[384*H];                    // [Wm1|Wi1]^T
__device__ __align__(16) __nv_bfloat16 g_Wi2T[H*H];
__device__ __align__(16) __nv_bfloat16 g_We1T[H2*H];
__device__ __align__(16) __nv_bfloat16 g_qkh[MROWS*512];                 // packed q|k bf16 (q pre-scaled)
__device__ __align__(16) __nv_bfloat16 g_i1b[MROWS*H];
__device__ __align__(16) __nv_bfloat16 g_fb[MROWS*H];
__device__ float g_str[B*S];
__device__ float g_awsum[B*S];
__device__ float g_awm[B*S];
__device__ float g_colmean[B*S];
__device__ float g_base[B*H];

// ---------------- PTX helpers ----------------
__device__ __forceinline__ uint32_t smem_u32(const void* p) {
    return (uint32_t)__cvta_generic_to_shared(p);
}
__device__ __forceinline__ void ldm_x4(uint32_t* r, uint32_t a) {
    asm volatile("ldmatrix.sync.aligned.m8n8.x4.shared.b16 {%0,%1,%2,%3}, [%4];"
        : "=r"(r[0]), "=r"(r[1]), "=r"(r[2]), "=r"(r[3]) : "r"(a));
}
__device__ __forceinline__ void mma_bf16(float* c, const uint32_t* a, const uint32_t* b) {
    asm volatile(
        "mma.sync.aligned.m16n8k16.row.col.f32.bf16.bf16.f32 "
        "{%0,%1,%2,%3},{%4,%5,%6,%7},{%8,%9},{%0,%1,%2,%3};"
        : "+f"(c[0]), "+f"(c[1]), "+f"(c[2]), "+f"(c[3])
        : "r"(a[0]), "r"(a[1]), "r"(a[2]), "r"(a[3]), "r"(b[0]), "r"(b[1]));
}
__device__ __forceinline__ void cpa16(uint32_t dst, const void* src) {
    asm volatile("cp.async.cg.shared.global [%0], [%1], 16;" :: "r"(dst), "l"(src));
}
__device__ __forceinline__ void cpa_commit() { asm volatile("cp.async.commit_group;"); }
__device__ __forceinline__ void cpa_wait1() { asm volatile("cp.async.wait_group 1;"); }
__device__ __forceinline__ void cpa_wait0() { asm volatile("cp.async.wait_group 0;"); }

__device__ __forceinline__ uint32_t h2_ex2(uint32_t x) {
    uint32_t r; asm("ex2.approx.f16x2 %0, %1;" : "=r"(r) : "r"(x)); return r;
}
__device__ __forceinline__ uint32_t h2_pack(float a, float b) {
    __half2 h = __floats2half2_rn(a, b);
    return *reinterpret_cast<uint32_t*>(&h);
}
__device__ __forceinline__ float2 h2_unpack(uint32_t u) {
    return __half22float2(*reinterpret_cast<__half2*>(&u));
}

// ---------------- fused prep ----------------
__global__ void prep_k(const float* __restrict__ x,
                       const float* __restrict__ Wq, const float* __restrict__ Wk,
                       const float* __restrict__ Wm1, const float* __restrict__ Wi1,
                       const float* __restrict__ Wi2, const float* __restrict__ We1) {
    int bid = blockIdx.x, t = threadIdx.x;
    if (bid < 4096) {
        int i = bid * 1024 + t * 4;
        float4 v = *(const float4*)(x + i);
        __nv_bfloat162* dst = (__nv_bfloat162*)(g_xh + i);
        dst[0] = __floats2bfloat162_rn(v.x, v.y);
        dst[1] = __floats2bfloat162_rn(v.z, v.w);
        return;
    }
    bid -= 4096;
    if (bid < 256) {
        int o = bid * 256 + t; int n = o >> 8, k = o & 255;
        g_WqkT[o] = __float2bfloat16(Wq[k * 256 + n]);
        return;
    }
    bid -= 256;
    if (bid < 256) {
        int o = bid * 256 + t; int n = o >> 8, k = o & 255;
        g_WqkT[65536 + o] = __float2bfloat16(Wk[k * 256 + n]);
        return;
    }
    bid -= 256;
    if (bid < 128) {
        int o = bid * 256 + t; int n = o >> 8, k = o & 255;
        g_WmiT[o] = __float2bfloat16(Wm1[k * 128 + n]);
        return;
    }
    bid -= 128;
    if (bid < 256) {
        int o = bid * 256 + t; int n = o >> 8, k = o & 255;
        g_WmiT[128 * 256 + o] = __float2bfloat16(Wi1[k * 256 + n]);
        return;
    }
    bid -= 256;
    if (bid < 256) {
        int o = bid * 256 + t; int n = o >> 8, k = o & 255;
        g_Wi2T[o] = __float2bfloat16(Wi2[k * 256 + n]);
        return;
    }
    bid -= 256;
    if (bid < 128) {
        int o = bid * 256 + t; int n = o >> 8, k = o & 255;
        g_We1T[o] = __float2bfloat16(We1[k * 128 + n]);
        return;
    }
    bid -= 128;
    if (bid < 64) {
        g_awsum[bid * 256 + t] = 0.f;
        return;
    }
    bid -= 64;
    g_base[bid * 256 + t] = 0.f;
}

// ---------------- shared GEMM pipeline body --------------------------------------
__device__ __forceinline__ void gemm_core(
    const __nv_bfloat16* __restrict__ Ah, const __nv_bfloat16* __restrict__ Bt,
    int row0, uint32_t sbase, int t, int wm, int wn, int lane,
    float acc[4][4][4])
{
    const int STB = 16384;
    auto load_stage = [&](int stage, int kt) {
        uint32_t sb = sbase + stage * STB;
#pragma unroll
        for (int i = 0; i < 2; i++) {
            int c = t + i * 256;
            int row = c >> 2, ch = c & 3;
            uint32_t d = (uint32_t)((row * 4 + (ch ^ ((row >> 1) & 3))) * 16);
            cpa16(sb + d, Ah + (size_t)(row0 + row) * 256 + kt * 32 + ch * 8);
            cpa16(sb + 8192 + d, Bt + (size_t)row * 256 + kt * 32 + ch * 8);
        }
    };
    load_stage(0, 0);
    cpa_commit();
    for (int kt = 0; kt < 8; kt++) {
        int st = kt & 1;
        if (kt < 7) { load_stage(st ^ 1, kt + 1); cpa_commit(); cpa_wait1(); }
        else cpa_wait0();
        __syncthreads();
        uint32_t sb = sbase + st * STB;
#pragma unroll
        for (int kk = 0; kk < 2; kk++) {
            uint32_t ah[4][4];
#pragma unroll
            for (int mt = 0; mt < 4; mt++) {
                int row = wm * 64 + mt * 16 + (lane & 15);
                int ch = kk * 2 + (lane >> 4);
                uint32_t off = (uint32_t)((row * 4 + (ch ^ ((row >> 1) & 3))) * 16);
                ldm_x4(ah[mt], sb + off);
            }
            uint32_t bh[4][2];
#pragma unroll
            for (int p = 0; p < 2; p++) {
                int row = wn * 32 + p * 16 + (lane & 7) + 8 * (lane >> 4);
                int ch = kk * 2 + ((lane >> 3) & 1);
                uint32_t off = (uint32_t)((row * 4 + (ch ^ ((row >> 1) & 3))) * 16);
                uint32_t r4[4];
                ldm_x4(r4, sb + 8192 + off);
                bh[2 * p][0] = r4[0]; bh[2 * p][1] = r4[1];
                bh[2 * p + 1][0] = r4[2]; bh[2 * p + 1][1] = r4[3];
            }
#pragma unroll
            for (int mt = 0; mt < 4; mt++)
#pragma unroll
                for (int nt = 0; nt < 4; nt++)
                    mma_bf16(acc[mt][nt], ah[mt], bh[nt]);
        }
        __syncthreads();
    }
}

// ---------------- merged QK | M1(strengths) | I1 GEMM ----------------------------
__global__ void __launch_bounds__(256) gemm_qkmi(
    const __nv_bfloat16* __restrict__ Ah,
    const float* __restrict__ bq, const float* __restrict__ bk,
    const float* __restrict__ bm1, const float* __restrict__ bi1,
    const float* __restrict__ Wm2, const float* __restrict__ bm2)
{
    extern __shared__ char smem[];
    int t = threadIdx.x, w = t >> 5, lane = t & 31;
    int bx = blockIdx.x;
    int row0 = blockIdx.y * 128;
    int wm = w & 1, wn = w >> 1;
    int g = lane >> 2, tq = lane & 3;

    const __nv_bfloat16* Bt = (bx < 4) ? (g_WqkT + (size_t)bx * 128 * 256)
                                       : (g_WmiT + (size_t)(bx - 4) * 128 * 256);

    float acc[4][4][4];
#pragma unroll
    for (int mt = 0; mt < 4; mt++)
#pragma unroll
        for (int nt = 0; nt < 4; nt++)
#pragma unroll
            for (int r = 0; r < 4; r++) acc[mt][nt][r] = 0.f;

    gemm_core(Ah, Bt, row0, smem_u32(smem), t, wm, wn, lane, acc);

    bool head = (bx == 4);
    float* st = (float*)smem;

#pragma unroll
    for (int mt = 0; mt < 4; mt++) {
        int rl = wm * 64 + mt * 16 + g;
#pragma unroll
        for (int nt = 0; nt < 4; nt++) {
            int cl = wn * 32 + nt * 8 + 2 * tq;
#pragma unroll
            for (int half = 0; half < 2; half++) {
                int rr = row0 + rl + 8 * half;
                float v0 = acc[mt][nt][2 * half];
                float v1 = acc[mt][nt][2 * half + 1];
                if (bx < 4) {
                    int gcol = bx * 128 + cl;
                    bool isk = (gcol >= 256);
                    v0 += isk ? bk[gcol - 256] : bq[gcol];
                    v1 += isk ? bk[gcol - 255] : bq[gcol + 1];
                    if (!isk) { v0 *= CEXP; v1 *= CEXP; }
                    *(__nv_bfloat162*)(g_qkh + (size_t)rr * 512 + gcol) =
                        __floats2bfloat162_rn(v0, v1);
                } else if (head) {
                    v0 = fmaxf(v0 + bm1[cl], 0.f);
                    v1 = fmaxf(v1 + bm1[cl + 1], 0.f);
                    st[(rl + 8 * half) * 129 + cl] = v0;
                    st[(rl + 8 * half) * 129 + cl + 1] = v1;
                } else {
                    int c2 = (bx - 5) * 128 + cl;
                    v0 = fmaxf(v0 + bi1[c2], 0.f);
                    v1 = fmaxf(v1 + bi1[c2 + 1], 0.f);
                    *(__nv_bfloat162*)(g_i1b + (size_t)rr * 256 + c2) =
                        __floats2bfloat162_rn(v0, v1);
                }
            }
        }
    }

    if (head) {
        __syncthreads();
        float wv[4];
#pragma unroll
        for (int i = 0; i < 4; i++) wv[i] = Wm2[lane + 32 * i];
        float hbv = bm2[0];
#pragma unroll
        for (int rr = w * 16; rr < w * 16 + 16; rr++) {
            float s = 0.f;
#pragma unroll
            for (int i = 0; i < 4; i++) s += wv[i] * st[rr * 129 + lane + 32 * i];
#pragma unroll
            for (int o = 16; o; o >>= 1) s += __shfl_xor_sync(0xFFFFFFFFu, s, o);
            if (lane == 0)
                g_str[row0 + rr] = 1.f / (1.f + __expf(-(s + hbv)));
        }
    }
}

// ---------------- I2+feats (MODE 2, + fused cm writer blocks) and E1+credit ------
template<int MODE>
__global__ void __launch_bounds__(256) gemm_mma(
    const __nv_bfloat16* __restrict__ Ah,
    const __nv_bfloat16* __restrict__ BTh,
    const float* __restrict__ bias0,
    const float* __restrict__ hw, const float* __restrict__ hb,
    const float* __restrict__ fin,
    void* out0, float* __restrict__ cmout)
{
    extern __shared__ char smem[];
    int t = threadIdx.x, w = t >> 5, lane = t & 31;

    if (MODE == 2 && blockIdx.x >= 2) {
        int blk = (blockIdx.x - 2) * 128 + blockIdx.y;
        int j4 = t;
        for (int r = 0; r < 64; r++) {
            int bi = blk * 64 + r;
            int b = bi >> 10, i = bi & 1023;
            float stv = g_str[bi];
            float4 a = ((const float4*)(g_awm + b * S))[j4];
            int j = j4 * 4;
            float4 v;
            v.x = (i >= j)     ? a.x * stv : 0.f;
            v.y = (i >= j + 1) ? a.y * stv : 0.f;
            v.z = (i >= j + 2) ? a.z * stv : 0.f;
            v.w = (i >= j + 3) ? a.w * stv : 0.f;
            ((float4*)(cmout + (size_t)bi * S))[j4] = v;
        }
        return;
    }

    int row0 = blockIdx.y * 128, col0 = blockIdx.x * 128;
    int wm = w & 1, wn = w >> 1;
    int g = lane >> 2, tq = lane & 3;

    float acc[4][4][4];
#pragma unroll
    for (int mt = 0; mt < 4; mt++)
#pragma unroll
        for (int nt = 0; nt < 4; nt++)
#pragma unroll
            for (int r = 0; r < 4; r++) acc[mt][nt][r] = 0.f;

    gemm_core(Ah, BTh + (size_t)col0 * 256, row0, smem_u32(smem), t, wm, wn, lane, acc);

    float* st = (float*)smem;

#pragma unroll
    for (int mt = 0; mt < 4; mt++) {
        int rl = wm * 64 + mt * 16 + g;
#pragma unroll
        for (int nt = 0; nt < 4; nt++) {
            int cl = wn * 32 + nt * 8 + 2 * tq;
            int colb = col0 + cl;
#pragma unroll
            for (int half = 0; half < 2; half++) {
                int rr = row0 + rl + 8 * half;
                float v0 = acc[mt][nt][2 * half];
                float v1 = acc[mt][nt][2 * half + 1];
                if (MODE == 2) {
                    v0 = 0.1f * tanhf(v0 + bias0[colb]);
                    v1 = 0.1f * tanhf(v1 + bias0[colb + 1]);
                    float cmv = g_colmean[rr] * (1.f / S);
                    int bb = row0 >> 10;
                    float f0 = g_base[bb * H + colb] + v0 * cmv;
                    float f1 = g_base[bb * H + colb + 1] + v1 * cmv;
                    *(__nv_bfloat162*)((__nv_bfloat16*)out0 + (size_t)rr * 256 + colb) =
                        __floats2bfloat162_rn(f0, f1);
                } else {
                    v0 = fmaxf(v0 + bias0[colb], 0.f);
                    v1 = fmaxf(v1 + bias0[colb + 1], 0.f);
                    st[(rl + 8 * half) * 129 + cl] = v0;
                    st[(rl + 8 * half) * 129 + cl + 1] = v1;
                }
            }
        }
    }

    if (MODE == 3) {
        __syncthreads();
        float wv[4];
#pragma unroll
        for (int i = 0; i < 4; i++) wv[i] = hw[lane + 32 * i];
        float hbv = hb[0];
        int bb = row0 >> 10;
#pragma unroll
        for (int rr = w * 16; rr < w * 16 + 16; rr++) {
            float s = 0.f;
#pragma unroll
            for (int i = 0; i < 4; i++) s += wv[i] * st[rr * 129 + lane + 32 * i];
#pragma unroll
            for (int o = 16; o; o >>= 1) s += __shfl_xor_sync(0xFFFFFFFFu, s, o);
            if (lane == 0)
                ((float*)out0)[row0 + rr] = fin[bb] - (s + hbv);
        }
    }
}

// ---------------- attention: m32 x n16 warp tile (halved K LDSM) -----------------
// 8 warps: wn = w (cols wn*16..+16); each warp covers all 32 q rows (mt 0..1).
#define ES_PITCH 1048
#define ATTN_SMEM (32768 + 4096 + 32*ES_PITCH*2 + 1024 + 128)
__global__ void __launch_bounds__(256) attn_mma() {
    extern __shared__ char smem[];
    char* Kst = smem;
    char* Qh = smem + 32768;
    __half* Es = (__half*)(Qh + 4096);
    float* rpart = (float*)(smem + 32768 + 4096 + 32 * ES_PITCH * 2); // [8][32]
    float* rden = rpart + 256;

    int t = threadIdx.x, w = t >> 5, lane = t & 31;
    int qt = blockIdx.x & 31;
    int bh = blockIdx.x >> 5;
    int b = bh >> 2, h = bh & 3;
    int q0 = qt * 32;
    int wn = w;                         // 0..7, 16 cols each
    int g = lane >> 2, tq = lane & 3;

    uint32_t kbase = smem_u32(Kst);
    uint32_t qbase = smem_u32(Qh);

    // load Q tile (32x64), swizzled
    {
        int row = t >> 3, ch = t & 7;
        const __nv_bfloat16* sh = g_qkh + (size_t)(b * S + q0 + row) * 512 + h * DH + ch * 8;
        uint32_t d = (uint32_t)((row * 8 + (ch ^ (row & 7))) * 16);
        *(uint4*)(Qh + d) = *(const uint4*)sh;
    }

    auto load_K = [&](int stage, int kt) {
        uint32_t sbk = kbase + stage * 16384;
#pragma unroll
        for (int i = 0; i < 4; i++) {
            int c = t + i * 256;
            int j = c >> 3, ch = c & 7;
            uint32_t d = (uint32_t)((j * 8 + (ch ^ (j & 7))) * 16);
            size_t src = (size_t)(b * S + kt * 128 + j) * 512 + 256 + h * DH + ch * 8;
            cpa16(sbk + d, g_qkh + src);
        }
    };

    load_K(0, 0);
    cpa_commit();
    __syncthreads();                 // Q STS visible

    // hoist ALL Q fragments: 2 mt x 4 d16 (32 regs)
    uint32_t aq[2][4][4];
#pragma unroll
    for (int mt = 0; mt < 2; mt++)
#pragma unroll
        for (int d16 = 0; d16 < 4; d16++) {
            int row = mt * 16 + (lane & 15);
            int ch = d16 * 2 + (lane >> 4);
            uint32_t off = (uint32_t)((row * 8 + (ch ^ (row & 7))) * 16);
            ldm_x4(aq[mt][d16], qbase + off);
        }

    float rsum[4] = {0.f, 0.f, 0.f, 0.f};   // rows g, g+8, g+16, g+24

    for (int kt = 0; kt < 8; kt++) {
        int stg = kt & 1;
        if (kt < 7) { load_K(stg ^ 1, kt + 1); cpa_commit(); cpa_wait1(); }
        else cpa_wait0();
        __syncthreads();
        uint32_t sbk = kbase + stg * 16384;

        float acc[2][2][4];
#pragma unroll
        for (int mt = 0; mt < 2; mt++)
#pragma unroll
            for (int nt = 0; nt < 2; nt++)
#pragma unroll
                for (int r = 0; r < 4; r++) acc[mt][nt][r] = 0.f;

#pragma unroll
        for (int d16 = 0; d16 < 4; d16++) {
            // one B ldmatrix x4 per d16: 16 cols x 32 k
            int j = wn * 16 + (lane & 7) + 8 * (lane >> 4);
            int ch = d16 * 2 + ((lane >> 3) & 1);
            uint32_t off = (uint32_t)((j * 8 + (ch ^ (j & 7))) * 16);
            uint32_t r4[4];
            ldm_x4(r4, sbk + off);
            uint32_t bh2[2][2];
            bh2[0][0] = r4[0]; bh2[0][1] = r4[1];
            bh2[1][0] = r4[2]; bh2[1][1] = r4[3];
#pragma unroll
            for (int mt = 0; mt < 2; mt++)
#pragma unroll
                for (int nt = 0; nt < 2; nt++)
                    mma_bf16(acc[mt][nt], aq[mt][d16], bh2[nt]);
        }
#pragma unroll
        for (int mt = 0; mt < 2; mt++)
#pragma unroll
            for (int nt = 0; nt < 2; nt++) {
                int colb = kt * 128 + wn * 16 + nt * 8 + 2 * tq;
                uint32_t e0 = h2_ex2(h2_pack(acc[mt][nt][0], acc[mt][nt][1]));
                uint32_t e1 = h2_ex2(h2_pack(acc[mt][nt][2], acc[mt][nt][3]));
                float2 f0 = h2_unpack(e0);
                float2 f1 = h2_unpack(e1);
                rsum[mt * 2]     += f0.x + f0.y;
                rsum[mt * 2 + 1] += f1.x + f1.y;
                int r0 = mt * 16 + g;
                *(uint32_t*)&Es[r0 * ES_PITCH + colb] = e0;
                *(uint32_t*)&Es[(r0 + 8) * ES_PITCH + colb] = e1;
            }
        __syncthreads();
    }

    // row sums: reduce over tq lanes, then over 8 wn warps via smem
#pragma unroll
    for (int i = 0; i < 4; i++) {
        rsum[i] += __shfl_xor_sync(0xFFFFFFFFu, rsum[i], 1);
        rsum[i] += __shfl_xor_sync(0xFFFFFFFFu, rsum[i], 2);
    }
    if (tq == 0) {
#pragma unroll
        for (int i = 0; i < 4; i++)
            rpart[w * 32 + i * 8 + g] = rsum[i];
    }
    __syncthreads();
    if (t < 32) {
        float s = 0.f;
#pragma unroll
        for (int ww = 0; ww < 8; ww++) s += rpart[ww * 32 + t];
        rden[t] = 1.f / s;
    }
    __syncthreads();

#pragma unroll
    for (int jj = 0; jj < 2; jj++) {
        int j2 = t + jj * 256;
        float sx = 0.f, sy = 0.f;
#pragma unroll
        for (int r = 0; r < 32; r++) {
            float2 e = __half22float2(((__half2*)(Es + r * ES_PITCH))[j2]);
            float rd = rden[r];
            sx += e.x * rd;
            sy += e.y * rd;
        }
        atomicAdd(&g_awsum[b * S + 2 * j2], sx);
        atomicAdd(&g_awsum[b * S + 2 * j2 + 1], sy);
    }
}

// ---------------- colmean (redundant scan) + parallel base -----------------------
__global__ void __launch_bounds__(1024) colmean_base_k() {
    __shared__ float s0[1024], s1[1024], cmb[1024], bacc[4][256];
    int b = blockIdx.x, sc = blockIdx.y, j = threadIdx.x;
    s0[j] = g_str[b * S + j];
    __syncthreads();
    float* cur = s0; float* nxt = s1;
#pragma unroll
    for (int off = 1; off < 1024; off <<= 1) {
        float v = cur[j];
        if (j + off < 1024) v += cur[j + off];
        __syncthreads();
        nxt[j] = v;
        __syncthreads();
        float* tmp = cur; cur = nxt; nxt = tmp;
    }
    float awm = g_awsum[b * S + j] * (1.f / (NH * S));
    float cmv = awm * cur[j] * (1.f / S);
    if (sc == 0) {
        g_awm[b * S + j] = awm;
        g_colmean[b * S + j] = cmv;
    }
    cmb[j] = cmv;
    __syncthreads();
    int h = j & 255, sg = j >> 8;
    const __nv_bfloat16* xb = g_xh + (size_t)b * S * H;
    int sbeg = sc * 128 + sg * 32;
    float a = 0.f;
    for (int s = sbeg; s < sbeg + 32; s++)
        a += __bfloat162float(xb[(size_t)s * H + h]) * cmb[s];
    bacc[sg][h] = a;
    __syncthreads();
    if (j < 256)
        atomicAdd(&g_base[b * H + j],
                  (bacc[0][j] + bacc[1][j] + bacc[2][j] + bacc[3][j]) * (1.f / S));
}

// ---------------- launch ----------------
extern "C" void kernel_launch(void* const* d_in, const int* in_sizes, int n_in,
                              void* d_out, int out_size) {
    const float* x    = (const float*)d_in[0];
    const float* fin  = (const float*)d_in[1];
    const float* Wq   = (const float*)d_in[3];
    const float* bq   = (const float*)d_in[4];
    const float* Wk   = (const float*)d_in[5];
    const float* bk   = (const float*)d_in[6];
    const float* Wm1  = (const float*)d_in[7];
    const float* bm1  = (const float*)d_in[8];
    const float* Wm2  = (const float*)d_in[9];
    const float* bm2  = (const float*)d_in[10];
    const float* Wi1  = (const float*)d_in[11];
    const float* bi1  = (const float*)d_in[12];
    const float* Wi2  = (const float*)d_in[13];
    const float* bi2  = (const float*)d_in[14];
    const float* We1  = (const float*)d_in[15];
    const float* be1  = (const float*)d_in[16];
    const float* We2  = (const float*)d_in[17];
    const float* be2  = (const float*)d_in[18];
    float* out = (float*)d_out;

    __nv_bfloat16 *pxh, *pWi2T, *pWe1T, *pi1b, *pfb;
    cudaGetSymbolAddress((void**)&pxh, g_xh);
    cudaGetSymbolAddress((void**)&pWi2T, g_Wi2T);
    cudaGetSymbolAddress((void**)&pWe1T, g_We1T);
    cudaGetSymbolAddress((void**)&pi1b, g_i1b);
    cudaGetSymbolAddress((void**)&pfb, g_fb);

    const int SM_1P = 32768, SM_HEAD = 66048;
    cudaFuncSetAttribute(gemm_qkmi, cudaFuncAttributeMaxDynamicSharedMemorySize, SM_HEAD);
    cudaFuncSetAttribute(gemm_mma<2>, cudaFuncAttributeMaxDynamicSharedMemorySize, SM_1P);
    cudaFuncSetAttribute(gemm_mma<3>, cudaFuncAttributeMaxDynamicSharedMemorySize, SM_HEAD);
    cudaFuncSetAttribute(attn_mma, cudaFuncAttributeMaxDynamicSharedMemorySize, ATTN_SMEM);

    // 1. prep
    prep_k<<<5456, 256>>>(x, Wq, Wk, Wm1, Wi1, Wi2, We1);

    // 2. merged QK | strengths | I1
    gemm_qkmi<<<dim3(7,128), 256, SM_HEAD>>>(pxh, bq, bk, bm1, bi1, Wm2, bm2);

    // 3. attention column sums
    attn_mma<<<B*NH*32, 256, ATTN_SMEM>>>();

    // 4. colmean (scan) + base
    colmean_base_k<<<dim3(B,8), 1024>>>();

    // 5. I2 + fused feats + cm writers -> out[B*S:]
    gemm_mma<2><<<dim3(4,128), 256, SM_1P>>>(pi1b, pWi2T, bi2,
                                             nullptr, nullptr, nullptr, pfb, out + B*S);
    // 6. E1 + fused credit head -> out[0 : B*S]
    gemm_mma<3><<<dim3(1,128), 256, SM_HEAD>>>(pfb, pWe1T, be1,
                                               We2, be2, fin, out, nullptr);
}